// round 8
// baseline (speedup 1.0000x reference)
#include <cuda_runtime.h>
#include <cstdint>
#include <cstddef>

// Problem constants
#define BB   16
#define CC   64
#define NN   2048
#define KK   20
#define OUTC 64

// ---------------- scratch (no allocations allowed) ----------------
__device__ __align__(16) float g_xt[BB * NN * CC];     // x transposed: [b][n][c]
__device__ float g_sq[BB * NN];                        // squared norms (bit-exact vs ref)
__device__ int   g_idx[BB * NN * KK];                  // knn indices, ascending dist
__device__ __align__(16) float g_wp[21 * CC * OUTC];   // slot-major weights [slot][c][o]
__device__ float g_scale[OUTC];
__device__ float g_shift[OUTC];

// ---------------- prep: transpose x -> xt ----------------
__global__ void prep_xt_kernel(const float* __restrict__ x) {
    __shared__ float sm[64][129];
    int b = blockIdx.y, n0 = blockIdx.x * 128, t = threadIdx.x;
    const float* xb = x + (size_t)b * CC * NN;
#pragma unroll
    for (int c = 0; c < 64; c++)
        sm[c][t] = xb[(size_t)c * NN + n0 + t];
    __syncthreads();
    float* xtb = g_xt + ((size_t)b * NN + n0) * 64;
#pragma unroll 4
    for (int i = 0; i < 64; i++) {
        int flat = i * 128 + t;
        int c = flat & 63, p = flat >> 6;
        xtb[(size_t)p * 64 + c] = sm[c][p];
    }
}

// ---------------- sq: XLA:CPU + LLVM LoopVectorizer replica ----------------
// square+reduce loop vectorized for AArch64: VF=4 (NEON), IC=2 -> 8 lanes.
// (verified bit-exact in round 7)
__global__ __launch_bounds__(256) void sq_kernel() {
    int p = blockIdx.x * 256 + threadIdx.x;    // point index
    const float4* z = (const float4*)(g_xt + (size_t)p * 64);
    float a[8];
#pragma unroll
    for (int l = 0; l < 8; l++) a[l] = 0.f;
#pragma unroll
    for (int i = 0; i < 8; i++) {
        float4 v0 = z[2 * i];
        float4 v1 = z[2 * i + 1];
        a[0] = __fadd_rn(a[0], __fmul_rn(v0.x, v0.x));
        a[1] = __fadd_rn(a[1], __fmul_rn(v0.y, v0.y));
        a[2] = __fadd_rn(a[2], __fmul_rn(v0.z, v0.z));
        a[3] = __fadd_rn(a[3], __fmul_rn(v0.w, v0.w));
        a[4] = __fadd_rn(a[4], __fmul_rn(v1.x, v1.x));
        a[5] = __fadd_rn(a[5], __fmul_rn(v1.y, v1.y));
        a[6] = __fadd_rn(a[6], __fmul_rn(v1.z, v1.z));
        a[7] = __fadd_rn(a[7], __fmul_rn(v1.w, v1.w));
    }
    float t0 = __fadd_rn(a[0], a[4]);
    float t1 = __fadd_rn(a[1], a[5]);
    float t2 = __fadd_rn(a[2], a[6]);
    float t3 = __fadd_rn(a[3], a[7]);
    g_sq[p] = __fadd_rn(__fadd_rn(t0, t1), __fadd_rn(t2, t3));
}

// ---------------- prep: reorganize weights ----------------
__global__ void prep_w_kernel(const float* __restrict__ w) {
    int c = blockIdx.x;   // 0..63
    int o = threadIdx.x;  // 0..63
    const float* w1 = w + ((size_t)o * 128 + c) * 20;
    const float* w2 = w + ((size_t)o * 128 + 64 + c) * 20;
    float s = 0.f;
#pragma unroll
    for (int j = 0; j < 20; j++) {
        float a = w1[j], d = w2[j];
        s += a - d;
        g_wp[(size_t)(1 + j) * 4096 + c * 64 + o] = d;
    }
    g_wp[c * 64 + o] = s;
}

// ---------------- knn: split-candidate fused distance + top-20 ----------------
// Block = 128 threads = 4 warps x 32 queries. Warp s handles candidates
// [512s, 512s+512) for all 32 queries (lane = query). Each warp owns a private
// SMEM tile (syncwarp only in the main loop). Distances use the verified
// bit-exact arithmetic (sequential ascending single-accumulator fma; SMEM reads
// via float4 -> LDS.128 broadcast). Per-thread top-20 (order-independent),
// then per-thread selection sort + 4-way lexicographic merge = exact jax
// top_k (dist, idx) order.
__global__ __launch_bounds__(128) void knn_kernel() {
    __shared__ __align__(16) float tiles[4][32 * 64];   // per-warp candidate tile
    __shared__ float tsq[4][32];
    int b = blockIdx.y;
    int warp = threadIdx.x >> 5;       // split 0..3
    int lane = threadIdx.x & 31;       // query within block
    int q = blockIdx.x * 32 + lane;
    const float* xb = g_xt + (size_t)b * NN * 64;

    float qr[64];
    {
        const float4* qp = (const float4*)(xb + (size_t)q * 64);
#pragma unroll
        for (int k = 0; k < 16; k++) {
            float4 v = qp[k];
            qr[4 * k] = v.x; qr[4 * k + 1] = v.y; qr[4 * k + 2] = v.z; qr[4 * k + 3] = v.w;
        }
    }
    float sqq = g_sq[b * NN + q];

    const float INF = __int_as_float(0x7f800000);
    float kd[20]; int ki[20];
#pragma unroll
    for (int k = 0; k < 20; k++) { kd[k] = INF; ki[k] = 0x7fffffff; }
    float wd = INF; int wi = 0x7fffffff; int ws = 0;

    int cand0 = warp * 512;
    for (int t0 = cand0; t0 < cand0 + 512; t0 += 32) {
        __syncwarp();
        {
            const float4* src = (const float4*)(xb + (size_t)t0 * 64);
            float4* dst = (float4*)tiles[warp];
#pragma unroll
            for (int k = 0; k < 16; k++) dst[lane + 32 * k] = src[lane + 32 * k];
            tsq[warp][lane] = g_sq[b * NN + t0 + lane];
        }
        __syncwarp();
#pragma unroll 1
        for (int cc = 0; cc < 32; cc += 2) {
            const float4* cva = (const float4*)(tiles[warp] + cc * 64);
            const float4* cvb = cva + 16;
            float da = 0.f, db = 0.f;
#pragma unroll
            for (int k = 0; k < 16; k++) {
                float4 va = cva[k];
                float4 vb = cvb[k];
                da = __fmaf_rn(qr[4 * k    ], va.x, da);
                da = __fmaf_rn(qr[4 * k + 1], va.y, da);
                da = __fmaf_rn(qr[4 * k + 2], va.z, da);
                da = __fmaf_rn(qr[4 * k + 3], va.w, da);
                db = __fmaf_rn(qr[4 * k    ], vb.x, db);
                db = __fmaf_rn(qr[4 * k + 1], vb.y, db);
                db = __fmaf_rn(qr[4 * k + 2], vb.z, db);
                db = __fmaf_rn(qr[4 * k + 3], vb.w, db);
            }
            float ta = __fadd_rn(sqq, tsq[warp][cc]);
            float tb = __fadd_rn(sqq, tsq[warp][cc + 1]);
            float dsta = __fmaf_rn(-2.f, da, ta);
            float dstb = __fmaf_rn(-2.f, db, tb);
#pragma unroll
            for (int h = 0; h < 2; h++) {
                float dst = h ? dstb : dsta;
                int ci = t0 + cc + h;
                bool take = (ci != q) && (dst < wd || (dst == wd && ci < wi));
                if (take) {
#pragma unroll
                    for (int k = 0; k < 20; k++) if (k == ws) { kd[k] = dst; ki[k] = ci; }
                    wd = kd[0]; wi = ki[0]; ws = 0;
#pragma unroll
                    for (int k = 1; k < 20; k++) {
                        bool g = (kd[k] > wd) || (kd[k] == wd && ki[k] > wi);
                        if (g) { wd = kd[k]; wi = ki[k]; ws = k; }
                    }
                }
            }
        }
    }

    // All warps done with tiles -> reuse tile SMEM as merge buffers.
    __syncthreads();
    float* md = (float*)tiles;                 // [4*32][20] sorted dists
    int*   mi = (int*)(md + 4 * 32 * 20);      // [4*32][20] sorted idxs
    int myoff = (warp * 32 + lane) * 20;
#pragma unroll 1
    for (int s = 0; s < 20; s++) {
        float bd = kd[0]; int bi = ki[0]; int bs = 0;
#pragma unroll
        for (int k = 1; k < 20; k++) {
            bool l = (kd[k] < bd) || (kd[k] == bd && ki[k] < bi);
            if (l) { bd = kd[k]; bi = ki[k]; bs = k; }
        }
        md[myoff + s] = bd;
        mi[myoff + s] = bi;
#pragma unroll
        for (int k = 0; k < 20; k++) if (k == bs) { kd[k] = INF; ki[k] = 0x7fffffff; }
    }
    __syncthreads();

    // 4-way merge of sorted lists (warp 0, lane = query)
    if (warp == 0) {
        int p0 = 0, p1 = 0, p2 = 0, p3 = 0;
        int* outp = g_idx + ((size_t)b * NN + q) * 20;
#pragma unroll 1
        for (int s = 0; s < 20; s++) {
            float bd = INF; int bi = 0x7fffffff; int bs = 0;
#pragma unroll
            for (int w = 0; w < 4; w++) {
                int pw = (w == 0) ? p0 : (w == 1) ? p1 : (w == 2) ? p2 : p3;
                float d = (pw < 20) ? md[(w * 32 + lane) * 20 + pw] : INF;
                int   i = (pw < 20) ? mi[(w * 32 + lane) * 20 + pw] : 0x7fffffff;
                bool l = (d < bd) || (d == bd && i < bi);
                if (l) { bd = d; bi = i; bs = w; }
            }
            outp[s] = bi;
            if (bs == 0) p0++; else if (bs == 1) p1++; else if (bs == 2) p2++; else p3++;
        }
    }
}

// ---------------- edgeconv: gather + slotted GEMM ----------------
// Block: 64 points x 64 outputs. Thread: 2 points x 8 outputs (16 acc regs).
__global__ __launch_bounds__(256) void edgeconv_kernel(const float* __restrict__ bias,
                                                       float* __restrict__ out) {
    __shared__ __align__(16) float wsm[64 * 64];
    __shared__ __align__(16) float nb[64 * 66];   // pad 66 -> conflict-free strided reads
    __shared__ int idxs[64 * 20];

    int b = blockIdx.y;
    int n0 = blockIdx.x * 64;
    int tid = threadIdx.x;
    int og = tid & 7;        // output group: o = og*8 .. og*8+7
    int pg = tid >> 3;       // 0..31
    int p0 = pg * 2, p1 = pg * 2 + 1;
    const float* xb = g_xt + (size_t)b * NN * 64;

    for (int i = tid; i < 64 * 20; i += 256)
        idxs[i] = g_idx[((size_t)b * NN + n0 + (i / 20)) * 20 + (i % 20)];

    float4 a0a = {0, 0, 0, 0}, a0b = {0, 0, 0, 0};
    float4 a1a = {0, 0, 0, 0}, a1b = {0, 0, 0, 0};

    for (int slot = 0; slot < 21; slot++) {
        __syncthreads();
#pragma unroll
        for (int k = 0; k < 4; k++)
            ((float4*)wsm)[tid + 256 * k] =
                ((const float4*)(g_wp + (size_t)slot * 4096))[tid + 256 * k];
        {
            int pt = tid >> 2, tsub = tid & 3;
            int srcn = (slot == 0) ? (n0 + pt) : idxs[pt * 20 + slot - 1];
            const float2* s2 = (const float2*)(xb + (size_t)srcn * 64) + tsub * 8;
            float2* d2 = (float2*)(nb + pt * 66) + tsub * 8;
#pragma unroll
            for (int k = 0; k < 8; k++) d2[k] = s2[k];
        }
        __syncthreads();
#pragma unroll 2
        for (int c = 0; c < 64; c++) {
            const float4* wr = (const float4*)(wsm + c * 64);
            float4 w0 = wr[og * 2];
            float4 w1 = wr[og * 2 + 1];
            float v0 = nb[p0 * 66 + c];
            float v1 = nb[p1 * 66 + c];
            a0a.x = fmaf(v0, w0.x, a0a.x); a0a.y = fmaf(v0, w0.y, a0a.y);
            a0a.z = fmaf(v0, w0.z, a0a.z); a0a.w = fmaf(v0, w0.w, a0a.w);
            a0b.x = fmaf(v0, w1.x, a0b.x); a0b.y = fmaf(v0, w1.y, a0b.y);
            a0b.z = fmaf(v0, w1.z, a0b.z); a0b.w = fmaf(v0, w1.w, a0b.w);
            a1a.x = fmaf(v1, w0.x, a1a.x); a1a.y = fmaf(v1, w0.y, a1a.y);
            a1a.z = fmaf(v1, w0.z, a1a.z); a1a.w = fmaf(v1, w0.w, a1a.w);
            a1b.x = fmaf(v1, w1.x, a1b.x); a1b.y = fmaf(v1, w1.y, a1b.y);
            a1b.z = fmaf(v1, w1.z, a1b.z); a1b.w = fmaf(v1, w1.w, a1b.w);
        }
    }

    float4 bb0 = ((const float4*)bias)[og * 2];
    float4 bb1 = ((const float4*)bias)[og * 2 + 1];
    a0a.x += bb0.x; a0a.y += bb0.y; a0a.z += bb0.z; a0a.w += bb0.w;
    a0b.x += bb1.x; a0b.y += bb1.y; a0b.z += bb1.z; a0b.w += bb1.w;
    a1a.x += bb0.x; a1a.y += bb0.y; a1a.z += bb0.z; a1a.w += bb0.w;
    a1b.x += bb1.x; a1b.y += bb1.y; a1b.z += bb1.z; a1b.w += bb1.w;

    float* ob = out + (size_t)b * OUTC * NN;
    int o0 = og * 8;
    ob[(size_t)(o0 + 0) * NN + n0 + p0] = a0a.x;
    ob[(size_t)(o0 + 1) * NN + n0 + p0] = a0a.y;
    ob[(size_t)(o0 + 2) * NN + n0 + p0] = a0a.z;
    ob[(size_t)(o0 + 3) * NN + n0 + p0] = a0a.w;
    ob[(size_t)(o0 + 4) * NN + n0 + p0] = a0b.x;
    ob[(size_t)(o0 + 5) * NN + n0 + p0] = a0b.y;
    ob[(size_t)(o0 + 6) * NN + n0 + p0] = a0b.z;
    ob[(size_t)(o0 + 7) * NN + n0 + p0] = a0b.w;
    ob[(size_t)(o0 + 0) * NN + n0 + p1] = a1a.x;
    ob[(size_t)(o0 + 1) * NN + n0 + p1] = a1a.y;
    ob[(size_t)(o0 + 2) * NN + n0 + p1] = a1a.z;
    ob[(size_t)(o0 + 3) * NN + n0 + p1] = a1a.w;
    ob[(size_t)(o0 + 4) * NN + n0 + p1] = a1b.x;
    ob[(size_t)(o0 + 5) * NN + n0 + p1] = a1b.y;
    ob[(size_t)(o0 + 6) * NN + n0 + p1] = a1b.z;
    ob[(size_t)(o0 + 7) * NN + n0 + p1] = a1b.w;
}

// ---------------- batchnorm stats (one block per channel) ----------------
__global__ void bn_stats_kernel(const float* __restrict__ y,
                                const float* __restrict__ gamma,
                                const float* __restrict__ beta) {
    int o = blockIdx.x, tid = threadIdx.x;
    float s = 0.f, ss = 0.f;
    for (int b = 0; b < BB; b++) {
        const float* p = y + ((size_t)b * OUTC + o) * NN;
        for (int i = tid; i < NN; i += 256) {
            float v = p[i];
            s += v;
            ss = fmaf(v, v, ss);
        }
    }
#pragma unroll
    for (int off = 16; off; off >>= 1) {
        s  += __shfl_down_sync(0xffffffffu, s, off);
        ss += __shfl_down_sync(0xffffffffu, ss, off);
    }
    __shared__ float shs[8], shss[8];
    int w = tid >> 5;
    if ((tid & 31) == 0) { shs[w] = s; shss[w] = ss; }
    __syncthreads();
    if (tid == 0) {
        s = 0.f; ss = 0.f;
#pragma unroll
        for (int k = 0; k < 8; k++) { s += shs[k]; ss += shss[k]; }
        float inv = 1.f / 32768.f;
        float mean = s * inv;
        float var = fmaf(ss, inv, -mean * mean);
        float r = rsqrtf(var + 1e-5f);
        float sc = gamma[o] * r;
        g_scale[o] = sc;
        g_shift[o] = beta[o] - mean * sc;
    }
}

// ---------------- normalize + leaky relu ----------------
__global__ void bn_apply_kernel(float* __restrict__ y) {
    int i = blockIdx.x * 256 + threadIdx.x;
    int o = (i >> 11) & 63;
    float v = fmaf(y[i], g_scale[o], g_shift[o]);
    y[i] = v >= 0.f ? v : 0.2f * v;
}

// ---------------- launch ----------------
extern "C" void kernel_launch(void* const* d_in, const int* in_sizes, int n_in,
                              void* d_out, int out_size) {
    const float* x     = (const float*)d_in[0];  // (16, 64, 2048)
    const float* w     = (const float*)d_in[1];  // (64, 128, 20)
    const float* bias  = (const float*)d_in[2];  // (64,)
    const float* gamma = (const float*)d_in[3];  // (64,)
    const float* beta  = (const float*)d_in[4];  // (64,)
    float* out = (float*)d_out;                  // (16, 64, 2048)

    prep_xt_kernel<<<dim3(NN / 128, BB), 128>>>(x);
    sq_kernel<<<(BB * NN) / 256, 256>>>();
    prep_w_kernel<<<64, 64>>>(w);
    knn_kernel<<<dim3(NN / 32, BB), 128>>>();
    edgeconv_kernel<<<dim3(NN / 64, BB), 256>>>(bias, out);
    bn_stats_kernel<<<OUTC, 256>>>(out, gamma, beta);
    bn_apply_kernel<<<(BB * OUTC * NN) / 256, 256>>>(out);
}

// round 9
// speedup vs baseline: 1.2979x; 1.2979x over previous
#include <cuda_runtime.h>
#include <cstdint>
#include <cstddef>

// Problem constants
#define BB   16
#define CC   64
#define NN   2048
#define KK   20
#define OUTC 64

// ---------------- scratch (no allocations allowed) ----------------
__device__ __align__(16) float g_xt[BB * NN * CC];     // x transposed: [b][n][c]
__device__ float g_sq[BB * NN];                        // squared norms (bit-exact vs ref)
__device__ int   g_idx[BB * NN * KK];                  // knn indices, ascending dist
__device__ __align__(16) float g_wp[21 * CC * OUTC];   // slot-major weights [slot][c][o]
__device__ float g_scale[OUTC];
__device__ float g_shift[OUTC];

// ---------------- prep: transpose x -> xt ----------------
__global__ void prep_xt_kernel(const float* __restrict__ x) {
    __shared__ float sm[64][129];
    int b = blockIdx.y, n0 = blockIdx.x * 128, t = threadIdx.x;
    const float* xb = x + (size_t)b * CC * NN;
#pragma unroll
    for (int c = 0; c < 64; c++)
        sm[c][t] = xb[(size_t)c * NN + n0 + t];
    __syncthreads();
    float* xtb = g_xt + ((size_t)b * NN + n0) * 64;
#pragma unroll 4
    for (int i = 0; i < 64; i++) {
        int flat = i * 128 + t;
        int c = flat & 63, p = flat >> 6;
        xtb[(size_t)p * 64 + c] = sm[c][p];
    }
}

// ---------------- sq: XLA:CPU + LLVM LoopVectorizer replica ----------------
// VF=4 (NEON), IC=2 -> 8 mod-8 lanes; verified bit-exact in round 7.
__global__ __launch_bounds__(256) void sq_kernel() {
    int p = blockIdx.x * 256 + threadIdx.x;    // point index
    const float4* z = (const float4*)(g_xt + (size_t)p * 64);
    float a[8];
#pragma unroll
    for (int l = 0; l < 8; l++) a[l] = 0.f;
#pragma unroll
    for (int i = 0; i < 8; i++) {
        float4 v0 = z[2 * i];
        float4 v1 = z[2 * i + 1];
        a[0] = __fadd_rn(a[0], __fmul_rn(v0.x, v0.x));
        a[1] = __fadd_rn(a[1], __fmul_rn(v0.y, v0.y));
        a[2] = __fadd_rn(a[2], __fmul_rn(v0.z, v0.z));
        a[3] = __fadd_rn(a[3], __fmul_rn(v0.w, v0.w));
        a[4] = __fadd_rn(a[4], __fmul_rn(v1.x, v1.x));
        a[5] = __fadd_rn(a[5], __fmul_rn(v1.y, v1.y));
        a[6] = __fadd_rn(a[6], __fmul_rn(v1.z, v1.z));
        a[7] = __fadd_rn(a[7], __fmul_rn(v1.w, v1.w));
    }
    float t0 = __fadd_rn(a[0], a[4]);
    float t1 = __fadd_rn(a[1], a[5]);
    float t2 = __fadd_rn(a[2], a[6]);
    float t3 = __fadd_rn(a[3], a[7]);
    g_sq[p] = __fadd_rn(__fadd_rn(t0, t1), __fadd_rn(t2, t3));
}

// ---------------- prep: reorganize weights ----------------
__global__ void prep_w_kernel(const float* __restrict__ w) {
    int c = blockIdx.x;   // 0..63
    int o = threadIdx.x;  // 0..63
    const float* w1 = w + ((size_t)o * 128 + c) * 20;
    const float* w2 = w + ((size_t)o * 128 + 64 + c) * 20;
    float s = 0.f;
#pragma unroll
    for (int j = 0; j < 20; j++) {
        float a = w1[j], d = w2[j];
        s += a - d;
        g_wp[(size_t)(1 + j) * 4096 + c * 64 + o] = d;
    }
    g_wp[c * 64 + o] = s;
}

// monotonic float->uint map (strictly order-preserving incl. negatives)
__device__ __forceinline__ unsigned mono_f(float f) {
    unsigned u = __float_as_uint(f);
    return u ^ (((unsigned)((int)u >> 31)) | 0x80000000u);
}
__device__ __forceinline__ float unmono_f(unsigned m) {
    unsigned u = (m & 0x80000000u) ? (m ^ 0x80000000u) : ~m;
    return __uint_as_float(u);
}

// ---------------- knn: 4-way split + shared threshold + u64 keys ----------------
// Block = 128 threads = 4 warps x 32 queries; warp s scans candidates
// [512s, 512s+512) (lane = query). wth[lane] holds a published 20th-worst
// distance (any warp's) -> safe global prune; restores total insert work to
// the single-scan union (~1385 insert-iterations / 32 queries) while keeping
// 4x warp parallelism. (dist,idx) packed as monotonic u64 keys: comparisons
// identical to lexicographic (dist, idx) -> bit-exact jax top_k order.
__global__ __launch_bounds__(128) void knn_kernel() {
    __shared__ __align__(16) float tiles[4][32 * 64];   // per-warp candidate tile
    __shared__ float tsq[4][32];
    __shared__ float wth[32];                            // shared per-query threshold
    int b = blockIdx.y;
    int warp = threadIdx.x >> 5;       // slice 0..3
    int lane = threadIdx.x & 31;       // query within block
    int q = blockIdx.x * 32 + lane;
    const float* xb = g_xt + (size_t)b * NN * 64;

    if (threadIdx.x < 32) wth[threadIdx.x] = __int_as_float(0x7f800000);

    float qr[64];
    {
        const float4* qp = (const float4*)(xb + (size_t)q * 64);
#pragma unroll
        for (int k = 0; k < 16; k++) {
            float4 v = qp[k];
            qr[4 * k] = v.x; qr[4 * k + 1] = v.y; qr[4 * k + 2] = v.z; qr[4 * k + 3] = v.w;
        }
    }
    float sqq = g_sq[b * NN + q];
    __syncthreads();   // wth init visible

    unsigned long long kk[20];
#pragma unroll
    for (int k = 0; k < 20; k++) kk[k] = ~0ull;
    unsigned long long wk = ~0ull;    // current worst key
    int ws = 0;                       // its slot

    int cand0 = warp * 512;
    for (int t0 = cand0; t0 < cand0 + 512; t0 += 32) {
        __syncwarp();
        {
            const float4* src = (const float4*)(xb + (size_t)t0 * 64);
            float4* dst = (float4*)tiles[warp];
#pragma unroll
            for (int k = 0; k < 16; k++) dst[lane + 32 * k] = src[lane + 32 * k];
            tsq[warp][lane] = g_sq[b * NN + t0 + lane];
        }
        __syncwarp();
#pragma unroll 1
        for (int cc = 0; cc < 32; cc += 2) {
            const float4* cva = (const float4*)(tiles[warp] + cc * 64);
            const float4* cvb = cva + 16;
            float da = 0.f, db = 0.f;
#pragma unroll
            for (int k = 0; k < 16; k++) {
                float4 va = cva[k];
                float4 vb = cvb[k];
                da = __fmaf_rn(qr[4 * k    ], va.x, da);
                da = __fmaf_rn(qr[4 * k + 1], va.y, da);
                da = __fmaf_rn(qr[4 * k + 2], va.z, da);
                da = __fmaf_rn(qr[4 * k + 3], va.w, da);
                db = __fmaf_rn(qr[4 * k    ], vb.x, db);
                db = __fmaf_rn(qr[4 * k + 1], vb.y, db);
                db = __fmaf_rn(qr[4 * k + 2], vb.z, db);
                db = __fmaf_rn(qr[4 * k + 3], vb.w, db);
            }
            float dsta = __fmaf_rn(-2.f, da, __fadd_rn(sqq, tsq[warp][cc]));
            float dstb = __fmaf_rn(-2.f, db, __fadd_rn(sqq, tsq[warp][cc + 1]));
#pragma unroll
            for (int h = 0; h < 2; h++) {
                float dst = h ? dstb : dsta;
                int ci = t0 + cc + h;
                float th = wth[lane];
                bool pass = (ci != q) && !(dst > th);   // keep ties at threshold
                if (pass) {
                    unsigned long long key =
                        ((unsigned long long)mono_f(dst) << 32) | (unsigned)ci;
                    if (key < wk) {
                        unsigned long long nw = 0ull; int nws = 0;
#pragma unroll
                        for (int k = 0; k < 20; k++) {
                            if (k == ws) kk[k] = key;
                            if (kk[k] > nw) { nw = kk[k]; nws = k; }
                        }
                        wk = nw; ws = nws;
                        float wdist = unmono_f((unsigned)(wk >> 32));
                        if (wdist < wth[lane]) wth[lane] = wdist;  // benign race
                    }
                }
            }
        }
    }

    // sorted per-warp lists into SMEM (reuse tiles)
    __syncthreads();
    unsigned long long* mk = (unsigned long long*)tiles;   // [128][20]
    int base = (warp * 32 + lane) * 20;
#pragma unroll 1
    for (int s = 0; s < 20; s++) {
        unsigned long long bv = kk[0]; int bs = 0;
#pragma unroll
        for (int k = 1; k < 20; k++)
            if (kk[k] < bv) { bv = kk[k]; bs = k; }
        mk[base + s] = bv;
#pragma unroll
        for (int k = 0; k < 20; k++) if (k == bs) kk[k] = ~0ull;
    }
    __syncthreads();

    // 4-way merge by min key (warp 0, lane = query)
    if (warp == 0) {
        int p0 = 0, p1 = 0, p2 = 0, p3 = 0;
        int* outp = g_idx + ((size_t)b * NN + q) * 20;
#pragma unroll 1
        for (int s = 0; s < 20; s++) {
            unsigned long long bv = ~0ull; int bw = 0;
#pragma unroll
            for (int w = 0; w < 4; w++) {
                int pw = (w == 0) ? p0 : (w == 1) ? p1 : (w == 2) ? p2 : p3;
                unsigned long long v = (pw < 20) ? mk[(w * 32 + lane) * 20 + pw] : ~0ull;
                if (v < bv) { bv = v; bw = w; }
            }
            outp[s] = (int)(bv & 0xFFFFFFFFull);
            if (bw == 0) p0++; else if (bw == 1) p1++; else if (bw == 2) p2++; else p3++;
        }
    }
}

// ---------------- edgeconv: gather + slotted GEMM ----------------
__global__ __launch_bounds__(256) void edgeconv_kernel(const float* __restrict__ bias,
                                                       float* __restrict__ out) {
    __shared__ __align__(16) float wsm[64 * 64];
    __shared__ __align__(16) float nb[64 * 66];
    __shared__ int idxs[64 * 20];

    int b = blockIdx.y;
    int n0 = blockIdx.x * 64;
    int tid = threadIdx.x;
    int og = tid & 7;
    int pg = tid >> 3;
    int p0 = pg * 2, p1 = pg * 2 + 1;
    const float* xb = g_xt + (size_t)b * NN * 64;

    for (int i = tid; i < 64 * 20; i += 256)
        idxs[i] = g_idx[((size_t)b * NN + n0 + (i / 20)) * 20 + (i % 20)];

    float4 a0a = {0, 0, 0, 0}, a0b = {0, 0, 0, 0};
    float4 a1a = {0, 0, 0, 0}, a1b = {0, 0, 0, 0};

    for (int slot = 0; slot < 21; slot++) {
        __syncthreads();
#pragma unroll
        for (int k = 0; k < 4; k++)
            ((float4*)wsm)[tid + 256 * k] =
                ((const float4*)(g_wp + (size_t)slot * 4096))[tid + 256 * k];
        {
            int pt = tid >> 2, tsub = tid & 3;
            int srcn = (slot == 0) ? (n0 + pt) : idxs[pt * 20 + slot - 1];
            const float2* s2 = (const float2*)(xb + (size_t)srcn * 64) + tsub * 8;
            float2* d2 = (float2*)(nb + pt * 66) + tsub * 8;
#pragma unroll
            for (int k = 0; k < 8; k++) d2[k] = s2[k];
        }
        __syncthreads();
#pragma unroll 2
        for (int c = 0; c < 64; c++) {
            const float4* wr = (const float4*)(wsm + c * 64);
            float4 w0 = wr[og * 2];
            float4 w1 = wr[og * 2 + 1];
            float v0 = nb[p0 * 66 + c];
            float v1 = nb[p1 * 66 + c];
            a0a.x = fmaf(v0, w0.x, a0a.x); a0a.y = fmaf(v0, w0.y, a0a.y);
            a0a.z = fmaf(v0, w0.z, a0a.z); a0a.w = fmaf(v0, w0.w, a0a.w);
            a0b.x = fmaf(v0, w1.x, a0b.x); a0b.y = fmaf(v0, w1.y, a0b.y);
            a0b.z = fmaf(v0, w1.z, a0b.z); a0b.w = fmaf(v0, w1.w, a0b.w);
            a1a.x = fmaf(v1, w0.x, a1a.x); a1a.y = fmaf(v1, w0.y, a1a.y);
            a1a.z = fmaf(v1, w0.z, a1a.z); a1a.w = fmaf(v1, w0.w, a1a.w);
            a1b.x = fmaf(v1, w1.x, a1b.x); a1b.y = fmaf(v1, w1.y, a1b.y);
            a1b.z = fmaf(v1, w1.z, a1b.z); a1b.w = fmaf(v1, w1.w, a1b.w);
        }
    }

    float4 bb0 = ((const float4*)bias)[og * 2];
    float4 bb1 = ((const float4*)bias)[og * 2 + 1];
    a0a.x += bb0.x; a0a.y += bb0.y; a0a.z += bb0.z; a0a.w += bb0.w;
    a0b.x += bb1.x; a0b.y += bb1.y; a0b.z += bb1.z; a0b.w += bb1.w;
    a1a.x += bb0.x; a1a.y += bb0.y; a1a.z += bb0.z; a1a.w += bb0.w;
    a1b.x += bb1.x; a1b.y += bb1.y; a1b.z += bb1.z; a1b.w += bb1.w;

    float* ob = out + (size_t)b * OUTC * NN;
    int o0 = og * 8;
    ob[(size_t)(o0 + 0) * NN + n0 + p0] = a0a.x;
    ob[(size_t)(o0 + 1) * NN + n0 + p0] = a0a.y;
    ob[(size_t)(o0 + 2) * NN + n0 + p0] = a0a.z;
    ob[(size_t)(o0 + 3) * NN + n0 + p0] = a0a.w;
    ob[(size_t)(o0 + 4) * NN + n0 + p0] = a0b.x;
    ob[(size_t)(o0 + 5) * NN + n0 + p0] = a0b.y;
    ob[(size_t)(o0 + 6) * NN + n0 + p0] = a0b.z;
    ob[(size_t)(o0 + 7) * NN + n0 + p0] = a0b.w;
    ob[(size_t)(o0 + 0) * NN + n0 + p1] = a1a.x;
    ob[(size_t)(o0 + 1) * NN + n0 + p1] = a1a.y;
    ob[(size_t)(o0 + 2) * NN + n0 + p1] = a1a.z;
    ob[(size_t)(o0 + 3) * NN + n0 + p1] = a1a.w;
    ob[(size_t)(o0 + 4) * NN + n0 + p1] = a1b.x;
    ob[(size_t)(o0 + 5) * NN + n0 + p1] = a1b.y;
    ob[(size_t)(o0 + 6) * NN + n0 + p1] = a1b.z;
    ob[(size_t)(o0 + 7) * NN + n0 + p1] = a1b.w;
}

// ---------------- batchnorm stats (one block per channel) ----------------
__global__ void bn_stats_kernel(const float* __restrict__ y,
                                const float* __restrict__ gamma,
                                const float* __restrict__ beta) {
    int o = blockIdx.x, tid = threadIdx.x;
    float s = 0.f, ss = 0.f;
    for (int b = 0; b < BB; b++) {
        const float* p = y + ((size_t)b * OUTC + o) * NN;
        for (int i = tid; i < NN; i += 256) {
            float v = p[i];
            s += v;
            ss = fmaf(v, v, ss);
        }
    }
#pragma unroll
    for (int off = 16; off; off >>= 1) {
        s  += __shfl_down_sync(0xffffffffu, s, off);
        ss += __shfl_down_sync(0xffffffffu, ss, off);
    }
    __shared__ float shs[8], shss[8];
    int w = tid >> 5;
    if ((tid & 31) == 0) { shs[w] = s; shss[w] = ss; }
    __syncthreads();
    if (tid == 0) {
        s = 0.f; ss = 0.f;
#pragma unroll
        for (int k = 0; k < 8; k++) { s += shs[k]; ss += shss[k]; }
        float inv = 1.f / 32768.f;
        float mean = s * inv;
        float var = fmaf(ss, inv, -mean * mean);
        float r = rsqrtf(var + 1e-5f);
        float sc = gamma[o] * r;
        g_scale[o] = sc;
        g_shift[o] = beta[o] - mean * sc;
    }
}

// ---------------- normalize + leaky relu ----------------
__global__ void bn_apply_kernel(float* __restrict__ y) {
    int i = blockIdx.x * 256 + threadIdx.x;
    int o = (i >> 11) & 63;
    float v = fmaf(y[i], g_scale[o], g_shift[o]);
    y[i] = v >= 0.f ? v : 0.2f * v;
}

// ---------------- launch ----------------
extern "C" void kernel_launch(void* const* d_in, const int* in_sizes, int n_in,
                              void* d_out, int out_size) {
    const float* x     = (const float*)d_in[0];  // (16, 64, 2048)
    const float* w     = (const float*)d_in[1];  // (64, 128, 20)
    const float* bias  = (const float*)d_in[2];  // (64,)
    const float* gamma = (const float*)d_in[3];  // (64,)
    const float* beta  = (const float*)d_in[4];  // (64,)
    float* out = (float*)d_out;                  // (16, 64, 2048)

    prep_xt_kernel<<<dim3(NN / 128, BB), 128>>>(x);
    sq_kernel<<<(BB * NN) / 256, 256>>>();
    prep_w_kernel<<<64, 64>>>(w);
    knn_kernel<<<dim3(NN / 32, BB), 128>>>();
    edgeconv_kernel<<<dim3(NN / 64, BB), 256>>>(bias, out);
    bn_stats_kernel<<<OUTC, 256>>>(out, gamma, beta);
    bn_apply_kernel<<<(BB * OUTC * NN) / 256, 256>>>(out);
}

// round 10
// speedup vs baseline: 2.0266x; 1.5615x over previous
#include <cuda_runtime.h>
#include <cstdint>
#include <cstddef>

// Problem constants
#define BB   16
#define CC   64
#define NN   2048
#define KK   20
#define OUTC 64

// ---------------- scratch (no allocations allowed) ----------------
__device__ __align__(16) float g_xt[BB * NN * CC];     // x transposed: [b][n][c]
__device__ float g_sq[BB * NN];                        // squared norms (bit-exact vs ref)
__device__ int   g_idx[BB * NN * KK];                  // knn indices, ascending dist
__device__ __align__(16) float g_wp[21 * CC * OUTC];   // slot-major weights [slot][c][o]
__device__ float g_scale[OUTC];
__device__ float g_shift[OUTC];
__device__ __align__(16) float g_dist[(size_t)BB * NN * NN];  // staged distance matrix (256MB)

// ---------------- prep: transpose x -> xt ----------------
__global__ void prep_xt_kernel(const float* __restrict__ x) {
    __shared__ float sm[64][129];
    int b = blockIdx.y, n0 = blockIdx.x * 128, t = threadIdx.x;
    const float* xb = x + (size_t)b * CC * NN;
#pragma unroll
    for (int c = 0; c < 64; c++)
        sm[c][t] = xb[(size_t)c * NN + n0 + t];
    __syncthreads();
    float* xtb = g_xt + ((size_t)b * NN + n0) * 64;
#pragma unroll 4
    for (int i = 0; i < 64; i++) {
        int flat = i * 128 + t;
        int c = flat & 63, p = flat >> 6;
        xtb[(size_t)p * 64 + c] = sm[c][p];
    }
}

// ---------------- sq: XLA:CPU + LLVM LoopVectorizer replica ----------------
// VF=4 (NEON), IC=2 -> 8 mod-8 lanes; verified bit-exact in round 7.
__global__ __launch_bounds__(256) void sq_kernel() {
    int p = blockIdx.x * 256 + threadIdx.x;    // point index
    const float4* z = (const float4*)(g_xt + (size_t)p * 64);
    float a[8];
#pragma unroll
    for (int l = 0; l < 8; l++) a[l] = 0.f;
#pragma unroll
    for (int i = 0; i < 8; i++) {
        float4 v0 = z[2 * i];
        float4 v1 = z[2 * i + 1];
        a[0] = __fadd_rn(a[0], __fmul_rn(v0.x, v0.x));
        a[1] = __fadd_rn(a[1], __fmul_rn(v0.y, v0.y));
        a[2] = __fadd_rn(a[2], __fmul_rn(v0.z, v0.z));
        a[3] = __fadd_rn(a[3], __fmul_rn(v0.w, v0.w));
        a[4] = __fadd_rn(a[4], __fmul_rn(v1.x, v1.x));
        a[5] = __fadd_rn(a[5], __fmul_rn(v1.y, v1.y));
        a[6] = __fadd_rn(a[6], __fmul_rn(v1.z, v1.z));
        a[7] = __fadd_rn(a[7], __fmul_rn(v1.w, v1.w));
    }
    float t0 = __fadd_rn(a[0], a[4]);
    float t1 = __fadd_rn(a[1], a[5]);
    float t2 = __fadd_rn(a[2], a[6]);
    float t3 = __fadd_rn(a[3], a[7]);
    g_sq[p] = __fadd_rn(__fadd_rn(t0, t1), __fadd_rn(t2, t3));
}

// ---------------- prep: reorganize weights ----------------
__global__ void prep_w_kernel(const float* __restrict__ w) {
    int c = blockIdx.x;   // 0..63
    int o = threadIdx.x;  // 0..63
    const float* w1 = w + ((size_t)o * 128 + c) * 20;
    const float* w2 = w + ((size_t)o * 128 + 64 + c) * 20;
    float s = 0.f;
#pragma unroll
    for (int j = 0; j < 20; j++) {
        float a = w1[j], d = w2[j];
        s += a - d;
        g_wp[(size_t)(1 + j) * 4096 + c * 64 + o] = d;
    }
    g_wp[c * 64 + o] = s;
}

// ---------------- dist: staged Gram/distance matrix (symmetric) ----------------
// Tile GEMM 64x64 per block, 4x4 per thread. acc accumulated sequentially
// k=0..63 single-accumulator fmaf -> bitwise identical to the verified chain.
// dist = fma(-2, acc, fadd(sq_i, sq_j)). Exactly symmetric (fmul/fadd commute),
// so only upper-triangle tiles are computed; mirror tile stored transposed.
__global__ __launch_bounds__(256) void dist_kernel(const float* __restrict__ x) {
    int tj = blockIdx.x, ti = blockIdx.y, b = blockIdx.z;
    if (tj < ti) return;
    __shared__ __align__(16) float Xi[64][68];
    __shared__ __align__(16) float Xj[64][68];
    int t = threadIdx.x;
    int i0 = ti * 64, j0 = tj * 64;
    const float* xb = x + (size_t)b * CC * NN;   // x is [c][n] per batch
    {
        int c = t >> 2, part = t & 3;
        const float4* si = (const float4*)(xb + (size_t)c * NN + i0);
        const float4* sj = (const float4*)(xb + (size_t)c * NN + j0);
#pragma unroll
        for (int kk = 0; kk < 4; kk++) {
            int f = part + kk * 4;   // 0..15
            *(float4*)&Xi[c][f * 4] = si[f];
            *(float4*)&Xj[c][f * 4] = sj[f];
        }
    }
    __syncthreads();
    int tx = t & 15, ty = t >> 4;
    float acc[16];
#pragma unroll
    for (int k = 0; k < 16; k++) acc[k] = 0.f;
#pragma unroll 16
    for (int k = 0; k < 64; k++) {
        float4 a  = *(const float4*)&Xi[k][ty * 4];
        float4 bv = *(const float4*)&Xj[k][tx * 4];
        acc[0]  = __fmaf_rn(a.x, bv.x, acc[0]);
        acc[1]  = __fmaf_rn(a.x, bv.y, acc[1]);
        acc[2]  = __fmaf_rn(a.x, bv.z, acc[2]);
        acc[3]  = __fmaf_rn(a.x, bv.w, acc[3]);
        acc[4]  = __fmaf_rn(a.y, bv.x, acc[4]);
        acc[5]  = __fmaf_rn(a.y, bv.y, acc[5]);
        acc[6]  = __fmaf_rn(a.y, bv.z, acc[6]);
        acc[7]  = __fmaf_rn(a.y, bv.w, acc[7]);
        acc[8]  = __fmaf_rn(a.z, bv.x, acc[8]);
        acc[9]  = __fmaf_rn(a.z, bv.y, acc[9]);
        acc[10] = __fmaf_rn(a.z, bv.z, acc[10]);
        acc[11] = __fmaf_rn(a.z, bv.w, acc[11]);
        acc[12] = __fmaf_rn(a.w, bv.x, acc[12]);
        acc[13] = __fmaf_rn(a.w, bv.y, acc[13]);
        acc[14] = __fmaf_rn(a.w, bv.z, acc[14]);
        acc[15] = __fmaf_rn(a.w, bv.w, acc[15]);
    }
    float si[4], sj[4];
#pragma unroll
    for (int r = 0; r < 4; r++) si[r] = g_sq[b * NN + i0 + ty * 4 + r];
#pragma unroll
    for (int s = 0; s < 4; s++) sj[s] = g_sq[b * NN + j0 + tx * 4 + s];
    float o[16];
#pragma unroll
    for (int r = 0; r < 4; r++)
#pragma unroll
        for (int s = 0; s < 4; s++)
            o[r * 4 + s] = __fmaf_rn(-2.f, acc[r * 4 + s], __fadd_rn(si[r], sj[s]));
    float* db = g_dist + (size_t)b * NN * NN;
#pragma unroll
    for (int r = 0; r < 4; r++) {
        float4 v = {o[r * 4], o[r * 4 + 1], o[r * 4 + 2], o[r * 4 + 3]};
        *(float4*)&db[(size_t)(i0 + ty * 4 + r) * NN + j0 + tx * 4] = v;
    }
    if (ti != tj) {
#pragma unroll
        for (int s = 0; s < 4; s++) {
            float4 m = {o[s], o[4 + s], o[8 + s], o[12 + s]};
            *(float4*)&db[(size_t)(j0 + tx * 4 + s) * NN + i0 + ty * 4] = m;
        }
    }
}

// monotonic float->uint map (strictly order-preserving incl. negatives)
__device__ __forceinline__ unsigned mono_f(float f) {
    unsigned u = __float_as_uint(f);
    return u ^ (((unsigned)((int)u >> 31)) | 0x80000000u);
}

// ---------------- select: warp-cooperative exact top-20 ----------------
// One warp per query. Lanes 0..19 hold the sorted (ascending) top-20 as
// monotonic u64 (dist,idx) keys. Per 32 candidates: coalesced load + key
// compare + ballot; each passer inserted via shfl-broadcast + shfl-up shift
// (~10 warp ops). Exact lexicographic (dist, idx) order == jax top_k.
__global__ __launch_bounds__(256) void select_kernel() {
    int warp = threadIdx.x >> 5, lane = threadIdx.x & 31;
    int b = blockIdx.y;
    int q = blockIdx.x * 8 + warp;
    const float* row = g_dist + ((size_t)b * NN + q) * NN;

    unsigned long long lkey = ~0ull;   // lanes 0..19: sorted list; others sentinel
    unsigned long long th = ~0ull;     // current 20th-worst key (uniform)

#pragma unroll 4
    for (int t = 0; t < 64; t++) {
        int j = t * 32 + lane;
        float d = row[j];
        unsigned long long ck =
            ((unsigned long long)mono_f(d) << 32) | (unsigned)j;
        bool pass = (j != q) && (ck < th);
        unsigned bal = __ballot_sync(0xffffffffu, pass);
        while (bal) {
            int src = __ffs(bal) - 1;
            bal &= bal - 1;
            unsigned long long c2 = __shfl_sync(0xffffffffu, ck, src);
            if (c2 < th) {
                unsigned long long up = __shfl_up_sync(0xffffffffu, lkey, 1);
                if (lane < 20 && lkey > c2)
                    lkey = (lane == 0 || up <= c2) ? c2 : up;
                th = __shfl_sync(0xffffffffu, lkey, 19);
            }
        }
    }
    if (lane < 20)
        g_idx[((size_t)b * NN + q) * 20 + lane] = (int)(lkey & 0xffffffffu);
}

// ---------------- edgeconv: gather + slotted GEMM ----------------
__global__ __launch_bounds__(256) void edgeconv_kernel(const float* __restrict__ bias,
                                                       float* __restrict__ out) {
    __shared__ __align__(16) float wsm[64 * 64];
    __shared__ __align__(16) float nb[64 * 66];
    __shared__ int idxs[64 * 20];

    int b = blockIdx.y;
    int n0 = blockIdx.x * 64;
    int tid = threadIdx.x;
    int og = tid & 7;
    int pg = tid >> 3;
    int p0 = pg * 2, p1 = pg * 2 + 1;
    const float* xb = g_xt + (size_t)b * NN * 64;

    for (int i = tid; i < 64 * 20; i += 256)
        idxs[i] = g_idx[((size_t)b * NN + n0 + (i / 20)) * 20 + (i % 20)];

    float4 a0a = {0, 0, 0, 0}, a0b = {0, 0, 0, 0};
    float4 a1a = {0, 0, 0, 0}, a1b = {0, 0, 0, 0};

    for (int slot = 0; slot < 21; slot++) {
        __syncthreads();
#pragma unroll
        for (int k = 0; k < 4; k++)
            ((float4*)wsm)[tid + 256 * k] =
                ((const float4*)(g_wp + (size_t)slot * 4096))[tid + 256 * k];
        {
            int pt = tid >> 2, tsub = tid & 3;
            int srcn = (slot == 0) ? (n0 + pt) : idxs[pt * 20 + slot - 1];
            const float2* s2 = (const float2*)(xb + (size_t)srcn * 64) + tsub * 8;
            float2* d2 = (float2*)(nb + pt * 66) + tsub * 8;
#pragma unroll
            for (int k = 0; k < 8; k++) d2[k] = s2[k];
        }
        __syncthreads();
#pragma unroll 2
        for (int c = 0; c < 64; c++) {
            const float4* wr = (const float4*)(wsm + c * 64);
            float4 w0 = wr[og * 2];
            float4 w1 = wr[og * 2 + 1];
            float v0 = nb[p0 * 66 + c];
            float v1 = nb[p1 * 66 + c];
            a0a.x = fmaf(v0, w0.x, a0a.x); a0a.y = fmaf(v0, w0.y, a0a.y);
            a0a.z = fmaf(v0, w0.z, a0a.z); a0a.w = fmaf(v0, w0.w, a0a.w);
            a0b.x = fmaf(v0, w1.x, a0b.x); a0b.y = fmaf(v0, w1.y, a0b.y);
            a0b.z = fmaf(v0, w1.z, a0b.z); a0b.w = fmaf(v0, w1.w, a0b.w);
            a1a.x = fmaf(v1, w0.x, a1a.x); a1a.y = fmaf(v1, w0.y, a1a.y);
            a1a.z = fmaf(v1, w0.z, a1a.z); a1a.w = fmaf(v1, w0.w, a1a.w);
            a1b.x = fmaf(v1, w1.x, a1b.x); a1b.y = fmaf(v1, w1.y, a1b.y);
            a1b.z = fmaf(v1, w1.z, a1b.z); a1b.w = fmaf(v1, w1.w, a1b.w);
        }
    }

    float4 bb0 = ((const float4*)bias)[og * 2];
    float4 bb1 = ((const float4*)bias)[og * 2 + 1];
    a0a.x += bb0.x; a0a.y += bb0.y; a0a.z += bb0.z; a0a.w += bb0.w;
    a0b.x += bb1.x; a0b.y += bb1.y; a0b.z += bb1.z; a0b.w += bb1.w;
    a1a.x += bb0.x; a1a.y += bb0.y; a1a.z += bb0.z; a1a.w += bb0.w;
    a1b.x += bb1.x; a1b.y += bb1.y; a1b.z += bb1.z; a1b.w += bb1.w;

    float* ob = out + (size_t)b * OUTC * NN;
    int o0 = og * 8;
    ob[(size_t)(o0 + 0) * NN + n0 + p0] = a0a.x;
    ob[(size_t)(o0 + 1) * NN + n0 + p0] = a0a.y;
    ob[(size_t)(o0 + 2) * NN + n0 + p0] = a0a.z;
    ob[(size_t)(o0 + 3) * NN + n0 + p0] = a0a.w;
    ob[(size_t)(o0 + 4) * NN + n0 + p0] = a0b.x;
    ob[(size_t)(o0 + 5) * NN + n0 + p0] = a0b.y;
    ob[(size_t)(o0 + 6) * NN + n0 + p0] = a0b.z;
    ob[(size_t)(o0 + 7) * NN + n0 + p0] = a0b.w;
    ob[(size_t)(o0 + 0) * NN + n0 + p1] = a1a.x;
    ob[(size_t)(o0 + 1) * NN + n0 + p1] = a1a.y;
    ob[(size_t)(o0 + 2) * NN + n0 + p1] = a1a.z;
    ob[(size_t)(o0 + 3) * NN + n0 + p1] = a1a.w;
    ob[(size_t)(o0 + 4) * NN + n0 + p1] = a1b.x;
    ob[(size_t)(o0 + 5) * NN + n0 + p1] = a1b.y;
    ob[(size_t)(o0 + 6) * NN + n0 + p1] = a1b.z;
    ob[(size_t)(o0 + 7) * NN + n0 + p1] = a1b.w;
}

// ---------------- batchnorm stats (one block per channel) ----------------
__global__ void bn_stats_kernel(const float* __restrict__ y,
                                const float* __restrict__ gamma,
                                const float* __restrict__ beta) {
    int o = blockIdx.x, tid = threadIdx.x;
    float s = 0.f, ss = 0.f;
    for (int b = 0; b < BB; b++) {
        const float* p = y + ((size_t)b * OUTC + o) * NN;
        for (int i = tid; i < NN; i += 256) {
            float v = p[i];
            s += v;
            ss = fmaf(v, v, ss);
        }
    }
#pragma unroll
    for (int off = 16; off; off >>= 1) {
        s  += __shfl_down_sync(0xffffffffu, s, off);
        ss += __shfl_down_sync(0xffffffffu, ss, off);
    }
    __shared__ float shs[8], shss[8];
    int w = tid >> 5;
    if ((tid & 31) == 0) { shs[w] = s; shss[w] = ss; }
    __syncthreads();
    if (tid == 0) {
        s = 0.f; ss = 0.f;
#pragma unroll
        for (int k = 0; k < 8; k++) { s += shs[k]; ss += shss[k]; }
        float inv = 1.f / 32768.f;
        float mean = s * inv;
        float var = fmaf(ss, inv, -mean * mean);
        float r = rsqrtf(var + 1e-5f);
        float sc = gamma[o] * r;
        g_scale[o] = sc;
        g_shift[o] = beta[o] - mean * sc;
    }
}

// ---------------- normalize + leaky relu ----------------
__global__ void bn_apply_kernel(float* __restrict__ y) {
    int i = blockIdx.x * 256 + threadIdx.x;
    int o = (i >> 11) & 63;
    float v = fmaf(y[i], g_scale[o], g_shift[o]);
    y[i] = v >= 0.f ? v : 0.2f * v;
}

// ---------------- launch ----------------
extern "C" void kernel_launch(void* const* d_in, const int* in_sizes, int n_in,
                              void* d_out, int out_size) {
    const float* x     = (const float*)d_in[0];  // (16, 64, 2048)
    const float* w     = (const float*)d_in[1];  // (64, 128, 20)
    const float* bias  = (const float*)d_in[2];  // (64,)
    const float* gamma = (const float*)d_in[3];  // (64,)
    const float* beta  = (const float*)d_in[4];  // (64,)
    float* out = (float*)d_out;                  // (16, 64, 2048)

    prep_xt_kernel<<<dim3(NN / 128, BB), 128>>>(x);
    sq_kernel<<<(BB * NN) / 256, 256>>>();
    prep_w_kernel<<<64, 64>>>(w);
    dist_kernel<<<dim3(NN / 64, NN / 64, BB), 256>>>(x);
    select_kernel<<<dim3(NN / 8, BB), 256>>>();
    edgeconv_kernel<<<dim3(NN / 64, BB), 256>>>(bias, out);
    bn_stats_kernel<<<OUTC, 256>>>(out, gamma, beta);
    bn_apply_kernel<<<(BB * OUTC * NN) / 256, 256>>>(out);
}

// round 11
// speedup vs baseline: 2.5310x; 1.2489x over previous
#include <cuda_runtime.h>
#include <cstdint>
#include <cstddef>

// Problem constants
#define BB   16
#define CC   64
#define NN   2048
#define KK   20
#define OUTC 64

// ---------------- scratch (no allocations allowed) ----------------
__device__ __align__(16) float g_xt[BB * NN * CC];     // x transposed: [b][n][c]
__device__ float g_sq[BB * NN];                        // squared norms (bit-exact vs ref)
__device__ int   g_idx[BB * NN * KK];                  // knn indices, ascending dist
__device__ __align__(16) float g_wp[21 * CC * OUTC];   // slot-major weights [slot][c][o]
__device__ float g_scale[OUTC];
__device__ float g_shift[OUTC];
__device__ __align__(16) float g_dist[(size_t)BB * NN * NN];  // staged distance matrix (256MB)

// ---------------- prep: transpose x -> xt ----------------
__global__ void prep_xt_kernel(const float* __restrict__ x) {
    __shared__ float sm[64][129];
    int b = blockIdx.y, n0 = blockIdx.x * 128, t = threadIdx.x;
    const float* xb = x + (size_t)b * CC * NN;
#pragma unroll
    for (int c = 0; c < 64; c++)
        sm[c][t] = xb[(size_t)c * NN + n0 + t];
    __syncthreads();
    float* xtb = g_xt + ((size_t)b * NN + n0) * 64;
#pragma unroll 4
    for (int i = 0; i < 64; i++) {
        int flat = i * 128 + t;
        int c = flat & 63, p = flat >> 6;
        xtb[(size_t)p * 64 + c] = sm[c][p];
    }
}

// ---------------- sq: XLA:CPU + LLVM LoopVectorizer replica ----------------
// VF=4 (NEON), IC=2 -> 8 mod-8 lanes; verified bit-exact in round 7.
__global__ __launch_bounds__(256) void sq_kernel() {
    int p = blockIdx.x * 256 + threadIdx.x;    // point index
    const float4* z = (const float4*)(g_xt + (size_t)p * 64);
    float a[8];
#pragma unroll
    for (int l = 0; l < 8; l++) a[l] = 0.f;
#pragma unroll
    for (int i = 0; i < 8; i++) {
        float4 v0 = z[2 * i];
        float4 v1 = z[2 * i + 1];
        a[0] = __fadd_rn(a[0], __fmul_rn(v0.x, v0.x));
        a[1] = __fadd_rn(a[1], __fmul_rn(v0.y, v0.y));
        a[2] = __fadd_rn(a[2], __fmul_rn(v0.z, v0.z));
        a[3] = __fadd_rn(a[3], __fmul_rn(v0.w, v0.w));
        a[4] = __fadd_rn(a[4], __fmul_rn(v1.x, v1.x));
        a[5] = __fadd_rn(a[5], __fmul_rn(v1.y, v1.y));
        a[6] = __fadd_rn(a[6], __fmul_rn(v1.z, v1.z));
        a[7] = __fadd_rn(a[7], __fmul_rn(v1.w, v1.w));
    }
    float t0 = __fadd_rn(a[0], a[4]);
    float t1 = __fadd_rn(a[1], a[5]);
    float t2 = __fadd_rn(a[2], a[6]);
    float t3 = __fadd_rn(a[3], a[7]);
    g_sq[p] = __fadd_rn(__fadd_rn(t0, t1), __fadd_rn(t2, t3));
}

// ---------------- prep: reorganize weights ----------------
__global__ void prep_w_kernel(const float* __restrict__ w) {
    int c = blockIdx.x;   // 0..63
    int o = threadIdx.x;  // 0..63
    const float* w1 = w + ((size_t)o * 128 + c) * 20;
    const float* w2 = w + ((size_t)o * 128 + 64 + c) * 20;
    float s = 0.f;
#pragma unroll
    for (int j = 0; j < 20; j++) {
        float a = w1[j], d = w2[j];
        s += a - d;
        g_wp[(size_t)(1 + j) * 4096 + c * 64 + o] = d;
    }
    g_wp[c * 64 + o] = s;
}

// ---------------- dist: staged distance matrix, 128x128 tiles, 8x8/thread ----
// K staged in two 32-slices (34KB smem). Per output element the k-chain is
// sequential ascending single-accumulator fmaf -> bitwise identical to the
// verified distance. dist = fma(-2, acc, fadd(sq_i, sq_j)); exact symmetry ->
// upper-triangle tiles only, mirror stored transposed.
__global__ __launch_bounds__(256) void dist_kernel(const float* __restrict__ x) {
    int tj = blockIdx.x, ti = blockIdx.y, b = blockIdx.z;
    if (tj < ti) return;
    __shared__ __align__(16) float Xi[32][132];
    __shared__ __align__(16) float Xj[32][132];
    int t = threadIdx.x;
    int tx = t & 15, ty = t >> 4;
    int i0 = ti * 128, j0 = tj * 128;
    const float* xb = x + (size_t)b * CC * NN;   // x is [c][n] per batch

    float acc[64];
#pragma unroll
    for (int k = 0; k < 64; k++) acc[k] = 0.f;

    for (int k0 = 0; k0 < 64; k0 += 32) {
        __syncthreads();
        {
            int c = t >> 3, ch = t & 7;
            const float4* si = (const float4*)(xb + (size_t)(k0 + c) * NN + i0);
            const float4* sj = (const float4*)(xb + (size_t)(k0 + c) * NN + j0);
#pragma unroll
            for (int u = 0; u < 4; u++) {
                *(float4*)&Xi[c][(ch + u * 8) * 4] = si[ch + u * 8];
                *(float4*)&Xj[c][(ch + u * 8) * 4] = sj[ch + u * 8];
            }
        }
        __syncthreads();
#pragma unroll 4
        for (int k = 0; k < 32; k++) {
            float4 a0 = *(const float4*)&Xi[k][ty * 8];
            float4 a1 = *(const float4*)&Xi[k][ty * 8 + 4];
            float4 b0 = *(const float4*)&Xj[k][tx * 8];
            float4 b1 = *(const float4*)&Xj[k][tx * 8 + 4];
            float av[8] = {a0.x, a0.y, a0.z, a0.w, a1.x, a1.y, a1.z, a1.w};
            float bv[8] = {b0.x, b0.y, b0.z, b0.w, b1.x, b1.y, b1.z, b1.w};
#pragma unroll
            for (int r = 0; r < 8; r++)
#pragma unroll
                for (int s = 0; s < 8; s++)
                    acc[r * 8 + s] = __fmaf_rn(av[r], bv[s], acc[r * 8 + s]);
        }
    }

    float si[8], sj[8];
#pragma unroll
    for (int r = 0; r < 8; r++) si[r] = g_sq[b * NN + i0 + ty * 8 + r];
#pragma unroll
    for (int s = 0; s < 8; s++) sj[s] = g_sq[b * NN + j0 + tx * 8 + s];
    float* db = g_dist + (size_t)b * NN * NN;
#pragma unroll
    for (int r = 0; r < 8; r++) {
        float o[8];
#pragma unroll
        for (int s = 0; s < 8; s++)
            o[s] = __fmaf_rn(-2.f, acc[r * 8 + s], __fadd_rn(si[r], sj[s]));
        *(float4*)&db[(size_t)(i0 + ty * 8 + r) * NN + j0 + tx * 8] =
            make_float4(o[0], o[1], o[2], o[3]);
        *(float4*)&db[(size_t)(i0 + ty * 8 + r) * NN + j0 + tx * 8 + 4] =
            make_float4(o[4], o[5], o[6], o[7]);
    }
    if (ti != tj) {
#pragma unroll
        for (int s = 0; s < 8; s++) {
            float m[8];
#pragma unroll
            for (int r = 0; r < 8; r++)
                m[r] = __fmaf_rn(-2.f, acc[r * 8 + s], __fadd_rn(si[r], sj[s]));
            *(float4*)&db[(size_t)(j0 + tx * 8 + s) * NN + i0 + ty * 8] =
                make_float4(m[0], m[1], m[2], m[3]);
            *(float4*)&db[(size_t)(j0 + tx * 8 + s) * NN + i0 + ty * 8 + 4] =
                make_float4(m[4], m[5], m[6], m[7]);
        }
    }
}

// monotonic float->uint map (strictly order-preserving incl. negatives)
__device__ __forceinline__ unsigned mono_f(float f) {
    unsigned u = __float_as_uint(f);
    return u ^ (((unsigned)((int)u >> 31)) | 0x80000000u);
}

// ---------------- select: warp-cooperative exact top-20 ----------------
__global__ __launch_bounds__(256) void select_kernel() {
    int warp = threadIdx.x >> 5, lane = threadIdx.x & 31;
    int b = blockIdx.y;
    int q = blockIdx.x * 8 + warp;
    const float* row = g_dist + ((size_t)b * NN + q) * NN;

    unsigned long long lkey = ~0ull;
    unsigned long long th = ~0ull;

#pragma unroll 4
    for (int t = 0; t < 64; t++) {
        int j = t * 32 + lane;
        float d = row[j];
        unsigned long long ck =
            ((unsigned long long)mono_f(d) << 32) | (unsigned)j;
        bool pass = (j != q) && (ck < th);
        unsigned bal = __ballot_sync(0xffffffffu, pass);
        while (bal) {
            int src = __ffs(bal) - 1;
            bal &= bal - 1;
            unsigned long long c2 = __shfl_sync(0xffffffffu, ck, src);
            if (c2 < th) {
                unsigned long long up = __shfl_up_sync(0xffffffffu, lkey, 1);
                if (lane < 20 && lkey > c2)
                    lkey = (lane == 0 || up <= c2) ? c2 : up;
                th = __shfl_sync(0xffffffffu, lkey, 19);
            }
        }
    }
    if (lane < 20)
        g_idx[((size_t)b * NN + q) * 20 + lane] = (int)(lkey & 0xffffffffu);
}

// ---------------- edgeconv: gather + slotted GEMM ----------------
// Block: 64 points x 64 outputs, 128 threads. Thread: 4 points x 8 outputs
// (32 acc). c unrolled x4 with float4 v loads -> 12 LDS.128 per 128 FFMA.
__global__ __launch_bounds__(128) void edgeconv_kernel(const float* __restrict__ bias,
                                                       float* __restrict__ out) {
    __shared__ __align__(16) float wsm[64 * 64];    // [c][o]
    __shared__ __align__(16) float nb[64 * 68];     // [pt][c], padded row 68
    __shared__ int idxs[64 * 20];

    int b = blockIdx.y;
    int n0 = blockIdx.x * 64;
    int tid = threadIdx.x;
    int og = tid & 7;        // output group: o = og*8 .. og*8+7
    int pg = tid >> 3;       // 0..15, points pg*4 .. pg*4+3
    const float* xb = g_xt + (size_t)b * NN * 64;

    for (int i = tid; i < 64 * 20; i += 128)
        idxs[i] = g_idx[((size_t)b * NN + n0 + (i / 20)) * 20 + (i % 20)];

    float acc[32];
#pragma unroll
    for (int k = 0; k < 32; k++) acc[k] = 0.f;

    for (int slot = 0; slot < 21; slot++) {
        __syncthreads();
#pragma unroll
        for (int k = 0; k < 8; k++)
            ((float4*)wsm)[tid + 128 * k] =
                ((const float4*)(g_wp + (size_t)slot * 4096))[tid + 128 * k];
        {
            int pt = tid >> 1, half = tid & 1;
            int srcn = (slot == 0) ? (n0 + pt) : idxs[pt * 20 + slot - 1];
            const float4* s4 = (const float4*)(xb + (size_t)srcn * 64) + half * 8;
            float4* d4 = (float4*)&nb[pt * 68] + half * 8;
#pragma unroll
            for (int u = 0; u < 8; u++) d4[u] = s4[u];
        }
        __syncthreads();
#pragma unroll 4
        for (int c4 = 0; c4 < 64; c4 += 4) {
            float va[4][4];
#pragma unroll
            for (int i = 0; i < 4; i++) {
                float4 v = *(const float4*)&nb[(pg * 4 + i) * 68 + c4];
                va[i][0] = v.x; va[i][1] = v.y; va[i][2] = v.z; va[i][3] = v.w;
            }
#pragma unroll
            for (int u = 0; u < 4; u++) {
                int c = c4 + u;
                float4 w0 = *(const float4*)&wsm[c * 64 + og * 8];
                float4 w1 = *(const float4*)&wsm[c * 64 + og * 8 + 4];
#pragma unroll
                for (int i = 0; i < 4; i++) {
                    float v = va[i][u];
                    acc[i * 8 + 0] = __fmaf_rn(v, w0.x, acc[i * 8 + 0]);
                    acc[i * 8 + 1] = __fmaf_rn(v, w0.y, acc[i * 8 + 1]);
                    acc[i * 8 + 2] = __fmaf_rn(v, w0.z, acc[i * 8 + 2]);
                    acc[i * 8 + 3] = __fmaf_rn(v, w0.w, acc[i * 8 + 3]);
                    acc[i * 8 + 4] = __fmaf_rn(v, w1.x, acc[i * 8 + 4]);
                    acc[i * 8 + 5] = __fmaf_rn(v, w1.y, acc[i * 8 + 5]);
                    acc[i * 8 + 6] = __fmaf_rn(v, w1.z, acc[i * 8 + 6]);
                    acc[i * 8 + 7] = __fmaf_rn(v, w1.w, acc[i * 8 + 7]);
                }
            }
        }
    }

    float bb[8];
    {
        float4 b0 = ((const float4*)bias)[og * 2];
        float4 b1 = ((const float4*)bias)[og * 2 + 1];
        bb[0] = b0.x; bb[1] = b0.y; bb[2] = b0.z; bb[3] = b0.w;
        bb[4] = b1.x; bb[5] = b1.y; bb[6] = b1.z; bb[7] = b1.w;
    }
    float* ob = out + (size_t)b * OUTC * NN;
#pragma unroll
    for (int o = 0; o < 8; o++) {
        float4 v = make_float4(acc[0 * 8 + o] + bb[o], acc[1 * 8 + o] + bb[o],
                               acc[2 * 8 + o] + bb[o], acc[3 * 8 + o] + bb[o]);
        *(float4*)&ob[(size_t)(og * 8 + o) * NN + n0 + pg * 4] = v;
    }
}

// ---------------- batchnorm stats (one block per channel) ----------------
__global__ void bn_stats_kernel(const float* __restrict__ y,
                                const float* __restrict__ gamma,
                                const float* __restrict__ beta) {
    int o = blockIdx.x, tid = threadIdx.x;
    float s = 0.f, ss = 0.f;
    for (int b = 0; b < BB; b++) {
        const float* p = y + ((size_t)b * OUTC + o) * NN;
        for (int i = tid; i < NN; i += 256) {
            float v = p[i];
            s += v;
            ss = fmaf(v, v, ss);
        }
    }
#pragma unroll
    for (int off = 16; off; off >>= 1) {
        s  += __shfl_down_sync(0xffffffffu, s, off);
        ss += __shfl_down_sync(0xffffffffu, ss, off);
    }
    __shared__ float shs[8], shss[8];
    int w = tid >> 5;
    if ((tid & 31) == 0) { shs[w] = s; shss[w] = ss; }
    __syncthreads();
    if (tid == 0) {
        s = 0.f; ss = 0.f;
#pragma unroll
        for (int k = 0; k < 8; k++) { s += shs[k]; ss += shss[k]; }
        float inv = 1.f / 32768.f;
        float mean = s * inv;
        float var = fmaf(ss, inv, -mean * mean);
        float r = rsqrtf(var + 1e-5f);
        float sc = gamma[o] * r;
        g_scale[o] = sc;
        g_shift[o] = beta[o] - mean * sc;
    }
}

// ---------------- normalize + leaky relu ----------------
__global__ void bn_apply_kernel(float* __restrict__ y) {
    int i = blockIdx.x * 256 + threadIdx.x;
    int o = (i >> 11) & 63;
    float v = fmaf(y[i], g_scale[o], g_shift[o]);
    y[i] = v >= 0.f ? v : 0.2f * v;
}

// ---------------- launch ----------------
extern "C" void kernel_launch(void* const* d_in, const int* in_sizes, int n_in,
                              void* d_out, int out_size) {
    const float* x     = (const float*)d_in[0];  // (16, 64, 2048)
    const float* w     = (const float*)d_in[1];  // (64, 128, 20)
    const float* bias  = (const float*)d_in[2];  // (64,)
    const float* gamma = (const float*)d_in[3];  // (64,)
    const float* beta  = (const float*)d_in[4];  // (64,)
    float* out = (float*)d_out;                  // (16, 64, 2048)

    prep_xt_kernel<<<dim3(NN / 128, BB), 128>>>(x);
    sq_kernel<<<(BB * NN) / 256, 256>>>();
    prep_w_kernel<<<64, 64>>>(w);
    dist_kernel<<<dim3(NN / 128, NN / 128, BB), 256>>>(x);
    select_kernel<<<dim3(NN / 8, BB), 256>>>();
    edgeconv_kernel<<<dim3(NN / 64, BB), 128>>>(bias, out);
    bn_stats_kernel<<<OUTC, 256>>>(out, gamma, beta);
    bn_apply_kernel<<<(BB * OUTC * NN) / 256, 256>>>(out);
}

// round 13
// speedup vs baseline: 3.1569x; 1.2473x over previous
#include <cuda_runtime.h>
#include <cuda_bf16.h>
#include <cstdint>
#include <cstddef>

// Problem constants
#define BB   16
#define CC   64
#define NN   2048
#define KK   20
#define OUTC 64

// ---------------- scratch (no allocations allowed) ----------------
__device__ __align__(16) float g_xt[BB * NN * CC];     // x transposed: [b][n][c]
__device__ float g_sq[BB * NN];                        // squared norms (bit-exact vs ref)
__device__ int   g_idx[BB * NN * KK];                  // knn indices, ascending dist
__device__ float g_scale[OUTC];
__device__ float g_shift[OUTC];
__device__ __align__(16) float g_dist[(size_t)BB * NN * NN];  // staged distance matrix (256MB)
// split-bf16 operands for tensor-core edgeconv
__device__ __align__(16) __nv_bfloat16 g_xhi[BB * NN * CC];   // [b][n][c]
__device__ __align__(16) __nv_bfloat16 g_xlo[BB * NN * CC];
__device__ __align__(16) __nv_bfloat16 g_wbh[21 * OUTC * CC]; // [slot][o][c]
__device__ __align__(16) __nv_bfloat16 g_wbl[21 * OUTC * CC];

// ---------------- prep: transpose x -> xt ----------------
__global__ void prep_xt_kernel(const float* __restrict__ x) {
    __shared__ float sm[64][129];
    int b = blockIdx.y, n0 = blockIdx.x * 128, t = threadIdx.x;
    const float* xb = x + (size_t)b * CC * NN;
#pragma unroll
    for (int c = 0; c < 64; c++)
        sm[c][t] = xb[(size_t)c * NN + n0 + t];
    __syncthreads();
    float* xtb = g_xt + ((size_t)b * NN + n0) * 64;
#pragma unroll 4
    for (int i = 0; i < 64; i++) {
        int flat = i * 128 + t;
        int c = flat & 63, p = flat >> 6;
        xtb[(size_t)p * 64 + c] = sm[c][p];
    }
}

// ---------------- split x into bf16 hi/lo ----------------
__global__ __launch_bounds__(256) void split_x_kernel() {
    int i = blockIdx.x * 256 + threadIdx.x;    // quad index
    float4 v = ((const float4*)g_xt)[i];
    float f[4] = {v.x, v.y, v.z, v.w};
    ushort4 hs, ls;
    unsigned short* hp = &hs.x;
    unsigned short* lp = &ls.x;
#pragma unroll
    for (int k = 0; k < 4; k++) {
        __nv_bfloat16 h = __float2bfloat16(f[k]);
        __nv_bfloat16 l = __float2bfloat16(f[k] - __bfloat162float(h));
        hp[k] = __bfloat16_as_ushort(h);
        lp[k] = __bfloat16_as_ushort(l);
    }
    ((ushort4*)g_xhi)[i] = hs;
    ((ushort4*)g_xlo)[i] = ls;
}

// ---------------- sq: XLA:CPU + LLVM LoopVectorizer replica ----------------
// VF=4 (NEON), IC=2 -> 8 mod-8 lanes; verified bit-exact in round 7.
__global__ __launch_bounds__(256) void sq_kernel() {
    int p = blockIdx.x * 256 + threadIdx.x;
    const float4* z = (const float4*)(g_xt + (size_t)p * 64);
    float a[8];
#pragma unroll
    for (int l = 0; l < 8; l++) a[l] = 0.f;
#pragma unroll
    for (int i = 0; i < 8; i++) {
        float4 v0 = z[2 * i];
        float4 v1 = z[2 * i + 1];
        a[0] = __fadd_rn(a[0], __fmul_rn(v0.x, v0.x));
        a[1] = __fadd_rn(a[1], __fmul_rn(v0.y, v0.y));
        a[2] = __fadd_rn(a[2], __fmul_rn(v0.z, v0.z));
        a[3] = __fadd_rn(a[3], __fmul_rn(v0.w, v0.w));
        a[4] = __fadd_rn(a[4], __fmul_rn(v1.x, v1.x));
        a[5] = __fadd_rn(a[5], __fmul_rn(v1.y, v1.y));
        a[6] = __fadd_rn(a[6], __fmul_rn(v1.z, v1.z));
        a[7] = __fadd_rn(a[7], __fmul_rn(v1.w, v1.w));
    }
    float t0 = __fadd_rn(a[0], a[4]);
    float t1 = __fadd_rn(a[1], a[5]);
    float t2 = __fadd_rn(a[2], a[6]);
    float t3 = __fadd_rn(a[3], a[7]);
    g_sq[p] = __fadd_rn(__fadd_rn(t0, t1), __fadd_rn(t2, t3));
}

// ---------------- prep: split weights -> bf16 hi/lo, [slot][o][c] ----------
// slot 0: w1sum[c][o] = sum_j (w[o][c][j] - w[o][C+c][j]); slot 1+j: w[o][C+c][j].
__global__ void prep_wb_kernel(const float* __restrict__ w) {
    int slot = blockIdx.x;
    for (int e = threadIdx.x; e < 4096; e += 256) {
        int o = e >> 6, c = e & 63;
        float val;
        if (slot == 0) {
            float s = 0.f;
            const float* w1 = w + ((size_t)o * 128 + c) * 20;
            const float* w2 = w + ((size_t)o * 128 + 64 + c) * 20;
#pragma unroll
            for (int j = 0; j < 20; j++) s += w1[j] - w2[j];
            val = s;
        } else {
            val = w[((size_t)o * 128 + 64 + c) * 20 + slot - 1];
        }
        __nv_bfloat16 h = __float2bfloat16(val);
        __nv_bfloat16 l = __float2bfloat16(val - __bfloat162float(h));
        g_wbh[slot * 4096 + o * 64 + c] = h;
        g_wbl[slot * 4096 + o * 64 + c] = l;
    }
}

// ---------------- dist: staged distance matrix, 128x128 tiles, 8x8/thread ----
__global__ __launch_bounds__(256) void dist_kernel(const float* __restrict__ x) {
    int tj = blockIdx.x, ti = blockIdx.y, b = blockIdx.z;
    if (tj < ti) return;
    __shared__ __align__(16) float Xi[32][132];
    __shared__ __align__(16) float Xj[32][132];
    int t = threadIdx.x;
    int tx = t & 15, ty = t >> 4;
    int i0 = ti * 128, j0 = tj * 128;
    const float* xb = x + (size_t)b * CC * NN;

    float acc[64];
#pragma unroll
    for (int k = 0; k < 64; k++) acc[k] = 0.f;

    for (int k0 = 0; k0 < 64; k0 += 32) {
        __syncthreads();
        {
            int c = t >> 3, ch = t & 7;
            const float4* si = (const float4*)(xb + (size_t)(k0 + c) * NN + i0);
            const float4* sj = (const float4*)(xb + (size_t)(k0 + c) * NN + j0);
#pragma unroll
            for (int u = 0; u < 4; u++) {
                *(float4*)&Xi[c][(ch + u * 8) * 4] = si[ch + u * 8];
                *(float4*)&Xj[c][(ch + u * 8) * 4] = sj[ch + u * 8];
            }
        }
        __syncthreads();
#pragma unroll 4
        for (int k = 0; k < 32; k++) {
            float4 a0 = *(const float4*)&Xi[k][ty * 8];
            float4 a1 = *(const float4*)&Xi[k][ty * 8 + 4];
            float4 b0 = *(const float4*)&Xj[k][tx * 8];
            float4 b1 = *(const float4*)&Xj[k][tx * 8 + 4];
            float av[8] = {a0.x, a0.y, a0.z, a0.w, a1.x, a1.y, a1.z, a1.w};
            float bv[8] = {b0.x, b0.y, b0.z, b0.w, b1.x, b1.y, b1.z, b1.w};
#pragma unroll
            for (int r = 0; r < 8; r++)
#pragma unroll
                for (int s = 0; s < 8; s++)
                    acc[r * 8 + s] = __fmaf_rn(av[r], bv[s], acc[r * 8 + s]);
        }
    }

    float si[8], sj[8];
#pragma unroll
    for (int r = 0; r < 8; r++) si[r] = g_sq[b * NN + i0 + ty * 8 + r];
#pragma unroll
    for (int s = 0; s < 8; s++) sj[s] = g_sq[b * NN + j0 + tx * 8 + s];
    float* db = g_dist + (size_t)b * NN * NN;
#pragma unroll
    for (int r = 0; r < 8; r++) {
        float o[8];
#pragma unroll
        for (int s = 0; s < 8; s++)
            o[s] = __fmaf_rn(-2.f, acc[r * 8 + s], __fadd_rn(si[r], sj[s]));
        *(float4*)&db[(size_t)(i0 + ty * 8 + r) * NN + j0 + tx * 8] =
            make_float4(o[0], o[1], o[2], o[3]);
        *(float4*)&db[(size_t)(i0 + ty * 8 + r) * NN + j0 + tx * 8 + 4] =
            make_float4(o[4], o[5], o[6], o[7]);
    }
    if (ti != tj) {
#pragma unroll
        for (int s = 0; s < 8; s++) {
            float m[8];
#pragma unroll
            for (int r = 0; r < 8; r++)
                m[r] = __fmaf_rn(-2.f, acc[r * 8 + s], __fadd_rn(si[r], sj[s]));
            *(float4*)&db[(size_t)(j0 + tx * 8 + s) * NN + i0 + ty * 8] =
                make_float4(m[0], m[1], m[2], m[3]);
            *(float4*)&db[(size_t)(j0 + tx * 8 + s) * NN + i0 + ty * 8 + 4] =
                make_float4(m[4], m[5], m[6], m[7]);
        }
    }
}

// monotonic float->uint map (strictly order-preserving incl. negatives)
__device__ __forceinline__ unsigned mono_f(float f) {
    unsigned u = __float_as_uint(f);
    return u ^ (((unsigned)((int)u >> 31)) | 0x80000000u);
}

// ---------------- select: warp-cooperative exact top-20 ----------------
__global__ __launch_bounds__(256) void select_kernel() {
    int warp = threadIdx.x >> 5, lane = threadIdx.x & 31;
    int b = blockIdx.y;
    int q = blockIdx.x * 8 + warp;
    const float* row = g_dist + ((size_t)b * NN + q) * NN;

    unsigned long long lkey = ~0ull;
    unsigned long long th = ~0ull;

#pragma unroll 4
    for (int t = 0; t < 64; t++) {
        int j = t * 32 + lane;
        float d = row[j];
        unsigned long long ck =
            ((unsigned long long)mono_f(d) << 32) | (unsigned)j;
        bool pass = (j != q) && (ck < th);
        unsigned bal = __ballot_sync(0xffffffffu, pass);
        while (bal) {
            int src = __ffs(bal) - 1;
            bal &= bal - 1;
            unsigned long long c2 = __shfl_sync(0xffffffffu, ck, src);
            if (c2 < th) {
                unsigned long long up = __shfl_up_sync(0xffffffffu, lkey, 1);
                if (lane < 20 && lkey > c2)
                    lkey = (lane == 0 || up <= c2) ? c2 : up;
                th = __shfl_sync(0xffffffffu, lkey, 19);
            }
        }
    }
    if (lane < 20)
        g_idx[((size_t)b * NN + q) * 20 + lane] = (int)(lkey & 0xffffffffu);
}

// ---------------- edgeconv: mma.sync split-bf16 slotted GEMM ----------------
// CTA = 128 points x 64 outputs, 8 warps. Warp w owns point rows
// [w*16, w*16+16) x all 64 outputs: 8 n-blocks x m16n8k16 mma, fp32 acc (32
// regs). 3 passes per slot: Ahi*Whi, Ahi*Wlo, Alo*Whi (lo*lo dropped,
// rel err ~2^-17). Fragments loaded directly from padded SMEM (no ldmatrix);
// padding 72 bf16/row -> conflict-free lane address patterns.
__device__ __forceinline__ void mma16816(float* c, uint32_t a0, uint32_t a1,
                                         uint32_t a2, uint32_t a3,
                                         uint32_t b0, uint32_t b1) {
    asm volatile(
        "mma.sync.aligned.m16n8k16.row.col.f32.bf16.bf16.f32 "
        "{%0,%1,%2,%3}, {%4,%5,%6,%7}, {%8,%9}, {%0,%1,%2,%3};"
        : "+f"(c[0]), "+f"(c[1]), "+f"(c[2]), "+f"(c[3])
        : "r"(a0), "r"(a1), "r"(a2), "r"(a3), "r"(b0), "r"(b1));
}

__global__ __launch_bounds__(256) void edgeconv_mma_kernel(const float* __restrict__ bias,
                                                           float* __restrict__ out) {
    __shared__ __align__(16) __nv_bfloat16 at[128][72];  // A tile (gathered rows)
    __shared__ __align__(16) __nv_bfloat16 wh[64][72];   // W hi  [o][c]
    __shared__ __align__(16) __nv_bfloat16 wl[64][72];   // W lo  [o][c]
    __shared__ int idxs[128 * 20];

    int tid = threadIdx.x, wid = tid >> 5, lane = tid & 31;
    int gid = lane >> 2, tig = lane & 3;
    int b = blockIdx.y, n0 = blockIdx.x * 128;
    const char* xhib = (const char*)g_xhi + (size_t)b * NN * 128;
    const char* xlob = (const char*)g_xlo + (size_t)b * NN * 128;

    for (int i = tid; i < 128 * 20; i += 256)
        idxs[i] = g_idx[((size_t)b * NN + n0 + i / 20) * 20 + (i % 20)];

    float acc[8][4];
#pragma unroll
    for (int j = 0; j < 8; j++)
#pragma unroll
        for (int k = 0; k < 4; k++) acc[j][k] = 0.f;

    int arow = wid * 16 + gid;

    for (int slot = 0; slot < 21; slot++) {
        __syncthreads();   // protect W + A from previous iteration readers
        // load W hi/lo tiles: 64 rows x 8 chunks of 8 bf16
#pragma unroll
        for (int i = 0; i < 2; i++) {
            int e = tid + 256 * i;
            int row = e >> 3, ch = e & 7;
            *(uint4*)&wh[row][ch * 8] =
                *(const uint4*)(g_wbh + slot * 4096 + row * 64 + ch * 8);
            *(uint4*)&wl[row][ch * 8] =
                *(const uint4*)(g_wbl + slot * 4096 + row * 64 + ch * 8);
        }
        // gather A hi: 128 rows x 8 chunks of 16B
#pragma unroll
        for (int u = 0; u < 4; u++) {
            int i = tid + 256 * u;
            int row = i >> 3, k = i & 7;
            int src = slot ? idxs[row * 20 + slot - 1] : n0 + row;
            *(uint4*)&at[row][k * 8] = *(const uint4*)(xhib + (size_t)src * 128 + k * 16);
        }
        __syncthreads();
        // passes hh + hl
#pragma unroll
        for (int kk = 0; kk < 4; kk++) {
            uint32_t a0 = *(const uint32_t*)&at[arow][kk * 16 + tig * 2];
            uint32_t a1 = *(const uint32_t*)&at[arow + 8][kk * 16 + tig * 2];
            uint32_t a2 = *(const uint32_t*)&at[arow][kk * 16 + tig * 2 + 8];
            uint32_t a3 = *(const uint32_t*)&at[arow + 8][kk * 16 + tig * 2 + 8];
#pragma unroll
            for (int j = 0; j < 8; j++) {
                uint32_t b0 = *(const uint32_t*)&wh[j * 8 + gid][kk * 16 + tig * 2];
                uint32_t b1 = *(const uint32_t*)&wh[j * 8 + gid][kk * 16 + tig * 2 + 8];
                mma16816(acc[j], a0, a1, a2, a3, b0, b1);
            }
#pragma unroll
            for (int j = 0; j < 8; j++) {
                uint32_t b0 = *(const uint32_t*)&wl[j * 8 + gid][kk * 16 + tig * 2];
                uint32_t b1 = *(const uint32_t*)&wl[j * 8 + gid][kk * 16 + tig * 2 + 8];
                mma16816(acc[j], a0, a1, a2, a3, b0, b1);
            }
        }
        __syncthreads();   // all warps done reading A-hi
        // gather A lo
#pragma unroll
        for (int u = 0; u < 4; u++) {
            int i = tid + 256 * u;
            int row = i >> 3, k = i & 7;
            int src = slot ? idxs[row * 20 + slot - 1] : n0 + row;
            *(uint4*)&at[row][k * 8] = *(const uint4*)(xlob + (size_t)src * 128 + k * 16);
        }
        __syncthreads();
        // pass lh
#pragma unroll
        for (int kk = 0; kk < 4; kk++) {
            uint32_t a0 = *(const uint32_t*)&at[arow][kk * 16 + tig * 2];
            uint32_t a1 = *(const uint32_t*)&at[arow + 8][kk * 16 + tig * 2];
            uint32_t a2 = *(const uint32_t*)&at[arow][kk * 16 + tig * 2 + 8];
            uint32_t a3 = *(const uint32_t*)&at[arow + 8][kk * 16 + tig * 2 + 8];
#pragma unroll
            for (int j = 0; j < 8; j++) {
                uint32_t b0 = *(const uint32_t*)&wh[j * 8 + gid][kk * 16 + tig * 2];
                uint32_t b1 = *(const uint32_t*)&wh[j * 8 + gid][kk * 16 + tig * 2 + 8];
                mma16816(acc[j], a0, a1, a2, a3, b0, b1);
            }
        }
    }

    // epilogue: D[pt][o]; c0,c1 -> (pt=arow, o=j*8+tig*2+{0,1}); c2,c3 -> pt=arow+8
    float* ob = out + (size_t)b * OUTC * NN;
#pragma unroll
    for (int j = 0; j < 8; j++) {
        int o0 = j * 8 + tig * 2;
        float bv0 = __ldg(bias + o0);
        float bv1 = __ldg(bias + o0 + 1);
        ob[(size_t)o0 * NN + n0 + arow]           = acc[j][0] + bv0;
        ob[(size_t)(o0 + 1) * NN + n0 + arow]     = acc[j][1] + bv1;
        ob[(size_t)o0 * NN + n0 + arow + 8]       = acc[j][2] + bv0;
        ob[(size_t)(o0 + 1) * NN + n0 + arow + 8] = acc[j][3] + bv1;
    }
}

// ---------------- batchnorm stats (one block per channel) ----------------
__global__ void bn_stats_kernel(const float* __restrict__ y,
                                const float* __restrict__ gamma,
                                const float* __restrict__ beta) {
    int o = blockIdx.x, tid = threadIdx.x;
    float s = 0.f, ss = 0.f;
    for (int b = 0; b < BB; b++) {
        const float* p = y + ((size_t)b * OUTC + o) * NN;
        for (int i = tid; i < NN; i += 256) {
            float v = p[i];
            s += v;
            ss = fmaf(v, v, ss);
        }
    }
#pragma unroll
    for (int off = 16; off; off >>= 1) {
        s  += __shfl_down_sync(0xffffffffu, s, off);
        ss += __shfl_down_sync(0xffffffffu, ss, off);
    }
    __shared__ float shs[8], shss[8];
    int w = tid >> 5;
    if ((tid & 31) == 0) { shs[w] = s; shss[w] = ss; }
    __syncthreads();
    if (tid == 0) {
        s = 0.f; ss = 0.f;
#pragma unroll
        for (int k = 0; k < 8; k++) { s += shs[k]; ss += shss[k]; }
        float inv = 1.f / 32768.f;
        float mean = s * inv;
        float var = fmaf(ss, inv, -mean * mean);
        float r = rsqrtf(var + 1e-5f);
        float sc = gamma[o] * r;
        g_scale[o] = sc;
        g_shift[o] = beta[o] - mean * sc;
    }
}

// ---------------- normalize + leaky relu ----------------
__global__ void bn_apply_kernel(float* __restrict__ y) {
    int i = blockIdx.x * 256 + threadIdx.x;
    int o = (i >> 11) & 63;
    float v = fmaf(y[i], g_scale[o], g_shift[o]);
    y[i] = v >= 0.f ? v : 0.2f * v;
}

// ---------------- launch ----------------
extern "C" void kernel_launch(void* const* d_in, const int* in_sizes, int n_in,
                              void* d_out, int out_size) {
    const float* x     = (const float*)d_in[0];  // (16, 64, 2048)
    const float* w     = (const float*)d_in[1];  // (64, 128, 20)
    const float* bias  = (const float*)d_in[2];  // (64,)
    const float* gamma = (const float*)d_in[3];  // (64,)
    const float* beta  = (const float*)d_in[4];  // (64,)
    float* out = (float*)d_out;                  // (16, 64, 2048)

    prep_xt_kernel<<<dim3(NN / 128, BB), 128>>>(x);
    sq_kernel<<<(BB * NN) / 256, 256>>>();
    split_x_kernel<<<(BB * NN * CC) / 4 / 256, 256>>>();
    prep_wb_kernel<<<21, 256>>>(w);
    dist_kernel<<<dim3(NN / 128, NN / 128, BB), 256>>>(x);
    select_kernel<<<dim3(NN / 8, BB), 256>>>();
    edgeconv_mma_kernel<<<dim3(NN / 128, BB), 256>>>(bias, out);
    bn_stats_kernel<<<OUTC, 256>>>(out, gamma, beta);
    bn_apply_kernel<<<(BB * OUTC * NN) / 256, 256>>>(out);
}

// round 14
// speedup vs baseline: 3.4619x; 1.0966x over previous
#include <cuda_runtime.h>
#include <cuda_bf16.h>
#include <cuda_fp16.h>
#include <cstdint>
#include <cstddef>

// Problem constants
#define BB   16
#define CC   64
#define NN   2048
#define KK   20
#define OUTC 64

// ---------------- scratch (no allocations allowed) ----------------
__device__ __align__(16) float g_xt[BB * NN * CC];     // x transposed: [b][n][c]
__device__ float g_sq[BB * NN];                        // squared norms (bit-exact vs ref)
__device__ int   g_idx[BB * NN * KK];                  // knn indices, ascending dist
__device__ int   g_cand[BB * NN * 32];                 // approx top-32 candidates
__device__ float g_scale[OUTC];
__device__ float g_shift[OUTC];
__device__ __align__(16) __half g_dh[(size_t)BB * NN * NN];   // approx distance (fp16, 128MB)
// split-bf16 operands for tensor-core kernels
__device__ __align__(16) __nv_bfloat16 g_xhi[BB * NN * CC];   // [b][n][c]
__device__ __align__(16) __nv_bfloat16 g_xlo[BB * NN * CC];
__device__ __align__(16) __nv_bfloat16 g_wbh[21 * OUTC * CC]; // [slot][o][c]
__device__ __align__(16) __nv_bfloat16 g_wbl[21 * OUTC * CC];

__device__ __forceinline__ void mma16816(float* c, uint32_t a0, uint32_t a1,
                                         uint32_t a2, uint32_t a3,
                                         uint32_t b0, uint32_t b1) {
    asm volatile(
        "mma.sync.aligned.m16n8k16.row.col.f32.bf16.bf16.f32 "
        "{%0,%1,%2,%3}, {%4,%5,%6,%7}, {%8,%9}, {%0,%1,%2,%3};"
        : "+f"(c[0]), "+f"(c[1]), "+f"(c[2]), "+f"(c[3])
        : "r"(a0), "r"(a1), "r"(a2), "r"(a3), "r"(b0), "r"(b1));
}

// monotonic float->uint map (strictly order-preserving incl. negatives)
__device__ __forceinline__ unsigned mono_f(float f) {
    unsigned u = __float_as_uint(f);
    return u ^ (((unsigned)((int)u >> 31)) | 0x80000000u);
}

// ---------------- prep: transpose x -> xt (+ bf16 hi/lo split) ----------------
__global__ void prep_xt_kernel(const float* __restrict__ x) {
    __shared__ float sm[64][129];
    int b = blockIdx.y, n0 = blockIdx.x * 128, t = threadIdx.x;
    const float* xb = x + (size_t)b * CC * NN;
#pragma unroll
    for (int c = 0; c < 64; c++)
        sm[c][t] = xb[(size_t)c * NN + n0 + t];
    __syncthreads();
    float* xtb = g_xt + ((size_t)b * NN + n0) * 64;
    __nv_bfloat16* xh = g_xhi + ((size_t)b * NN + n0) * 64;
    __nv_bfloat16* xl = g_xlo + ((size_t)b * NN + n0) * 64;
#pragma unroll 4
    for (int i = 0; i < 64; i++) {
        int flat = i * 128 + t;
        int c = flat & 63, p = flat >> 6;
        float v = sm[c][p];
        xtb[(size_t)p * 64 + c] = v;
        __nv_bfloat16 h = __float2bfloat16(v);
        xh[(size_t)p * 64 + c] = h;
        xl[(size_t)p * 64 + c] = __float2bfloat16(v - __bfloat162float(h));
    }
}

// ---------------- sq: XLA:CPU + LLVM LoopVectorizer replica ----------------
// VF=4 (NEON), IC=2 -> 8 mod-8 lanes; verified bit-exact in round 7.
__global__ __launch_bounds__(256) void sq_kernel() {
    int p = blockIdx.x * 256 + threadIdx.x;
    const float4* z = (const float4*)(g_xt + (size_t)p * 64);
    float a[8];
#pragma unroll
    for (int l = 0; l < 8; l++) a[l] = 0.f;
#pragma unroll
    for (int i = 0; i < 8; i++) {
        float4 v0 = z[2 * i];
        float4 v1 = z[2 * i + 1];
        a[0] = __fadd_rn(a[0], __fmul_rn(v0.x, v0.x));
        a[1] = __fadd_rn(a[1], __fmul_rn(v0.y, v0.y));
        a[2] = __fadd_rn(a[2], __fmul_rn(v0.z, v0.z));
        a[3] = __fadd_rn(a[3], __fmul_rn(v0.w, v0.w));
        a[4] = __fadd_rn(a[4], __fmul_rn(v1.x, v1.x));
        a[5] = __fadd_rn(a[5], __fmul_rn(v1.y, v1.y));
        a[6] = __fadd_rn(a[6], __fmul_rn(v1.z, v1.z));
        a[7] = __fadd_rn(a[7], __fmul_rn(v1.w, v1.w));
    }
    float t0 = __fadd_rn(a[0], a[4]);
    float t1 = __fadd_rn(a[1], a[5]);
    float t2 = __fadd_rn(a[2], a[6]);
    float t3 = __fadd_rn(a[3], a[7]);
    g_sq[p] = __fadd_rn(__fadd_rn(t0, t1), __fadd_rn(t2, t3));
}

// ---------------- prep: split weights -> bf16 hi/lo, [slot][o][c] ----------
__global__ void prep_wb_kernel(const float* __restrict__ w) {
    int slot = blockIdx.x;
    int e = blockIdx.y * 256 + threadIdx.x;   // 0..4095
    int o = e >> 6, c = e & 63;
    float val;
    if (slot == 0) {
        float s = 0.f;
        const float* w1 = w + ((size_t)o * 128 + c) * 20;
        const float* w2 = w + ((size_t)o * 128 + 64 + c) * 20;
#pragma unroll
        for (int j = 0; j < 20; j++) s += w1[j] - w2[j];
        val = s;
    } else {
        val = w[((size_t)o * 128 + 64 + c) * 20 + slot - 1];
    }
    __nv_bfloat16 h = __float2bfloat16(val);
    __nv_bfloat16 l = __float2bfloat16(val - __bfloat162float(h));
    g_wbh[slot * 4096 + o * 64 + c] = h;
    g_wbl[slot * 4096 + o * 64 + c] = l;
}

// ---------------- gram: approx distance matrix via mma.sync split-bf16 ------
// CTA tile 128(i) x 128(j), 8 warps: warp owns 16 i-rows x 128 j-cols
// (16 n-blocks of m16n8k16, fp32 acc). 3 passes: hh + hl + lh.
// dist = max(0, fma(-2, acc, sqi+sqj)) stored fp16. Full grid (no symmetry)
// so all stores are direct + coalesced.
__global__ __launch_bounds__(256) void gram_kernel() {
    extern __shared__ __align__(16) __nv_bfloat16 gsm[];
    __nv_bfloat16* ah = gsm;                   // [128][72]
    __nv_bfloat16* al = ah + 128 * 72;
    __nv_bfloat16* bh = al + 128 * 72;
    __nv_bfloat16* bl = bh + 128 * 72;

    int tid = threadIdx.x, wid = tid >> 5, lane = tid & 31;
    int gid = lane >> 2, tig = lane & 3;
    int b = blockIdx.z;
    int i0 = blockIdx.y * 128, j0 = blockIdx.x * 128;
    const uint4* xh = (const uint4*)(g_xhi + (size_t)b * NN * 64);  // 8 uint4 per row
    const uint4* xl = (const uint4*)(g_xlo + (size_t)b * NN * 64);

#pragma unroll
    for (int u = 0; u < 4; u++) {
        int e = tid + 256 * u;
        int r = e >> 3, ch = e & 7;
        *(uint4*)&ah[r * 72 + ch * 8] = xh[(size_t)(i0 + r) * 8 + ch];
        *(uint4*)&al[r * 72 + ch * 8] = xl[(size_t)(i0 + r) * 8 + ch];
        *(uint4*)&bh[r * 72 + ch * 8] = xh[(size_t)(j0 + r) * 8 + ch];
        *(uint4*)&bl[r * 72 + ch * 8] = xl[(size_t)(j0 + r) * 8 + ch];
    }
    __syncthreads();

    int arow = wid * 16 + gid;
    float acc[16][4];
#pragma unroll
    for (int nb = 0; nb < 16; nb++)
#pragma unroll
        for (int k = 0; k < 4; k++) acc[nb][k] = 0.f;

#pragma unroll
    for (int kk = 0; kk < 4; kk++) {
        int co = kk * 16 + tig * 2;
        uint32_t ah0 = *(const uint32_t*)&ah[arow * 72 + co];
        uint32_t ah1 = *(const uint32_t*)&ah[(arow + 8) * 72 + co];
        uint32_t ah2 = *(const uint32_t*)&ah[arow * 72 + co + 8];
        uint32_t ah3 = *(const uint32_t*)&ah[(arow + 8) * 72 + co + 8];
        uint32_t al0 = *(const uint32_t*)&al[arow * 72 + co];
        uint32_t al1 = *(const uint32_t*)&al[(arow + 8) * 72 + co];
        uint32_t al2 = *(const uint32_t*)&al[arow * 72 + co + 8];
        uint32_t al3 = *(const uint32_t*)&al[(arow + 8) * 72 + co + 8];
#pragma unroll
        for (int nb = 0; nb < 16; nb++) {
            uint32_t b0 = *(const uint32_t*)&bh[(nb * 8 + gid) * 72 + co];
            uint32_t b1 = *(const uint32_t*)&bh[(nb * 8 + gid) * 72 + co + 8];
            mma16816(acc[nb], ah0, ah1, ah2, ah3, b0, b1);
        }
#pragma unroll
        for (int nb = 0; nb < 16; nb++) {
            uint32_t b0 = *(const uint32_t*)&bl[(nb * 8 + gid) * 72 + co];
            uint32_t b1 = *(const uint32_t*)&bl[(nb * 8 + gid) * 72 + co + 8];
            mma16816(acc[nb], ah0, ah1, ah2, ah3, b0, b1);
        }
#pragma unroll
        for (int nb = 0; nb < 16; nb++) {
            uint32_t b0 = *(const uint32_t*)&bh[(nb * 8 + gid) * 72 + co];
            uint32_t b1 = *(const uint32_t*)&bh[(nb * 8 + gid) * 72 + co + 8];
            mma16816(acc[nb], al0, al1, al2, al3, b0, b1);
        }
    }

    float si0 = g_sq[b * NN + i0 + arow];
    float si8 = g_sq[b * NN + i0 + arow + 8];
    __half* db = g_dh + (size_t)b * NN * NN;
#pragma unroll
    for (int nb = 0; nb < 16; nb++) {
        int jj = j0 + nb * 8 + tig * 2;
        float sj0 = g_sq[b * NN + jj];
        float sj1 = g_sq[b * NN + jj + 1];
        float d00 = fmaxf(__fmaf_rn(-2.f, acc[nb][0], __fadd_rn(si0, sj0)), 0.f);
        float d01 = fmaxf(__fmaf_rn(-2.f, acc[nb][1], __fadd_rn(si0, sj1)), 0.f);
        float d80 = fmaxf(__fmaf_rn(-2.f, acc[nb][2], __fadd_rn(si8, sj0)), 0.f);
        float d81 = fmaxf(__fmaf_rn(-2.f, acc[nb][3], __fadd_rn(si8, sj1)), 0.f);
        *(__half2*)&db[(size_t)(i0 + arow) * NN + jj]     = __floats2half2_rn(d00, d01);
        *(__half2*)&db[(size_t)(i0 + arow + 8) * NN + jj] = __floats2half2_rn(d80, d81);
    }
}

// ---------------- select: warp-cooperative approx top-32 ----------------
// One warp per query; 32 sorted lanes hold u32 keys ((half_bits<<11)|j).
// Approx top-32 is a superset of the exact top-20 (err << rank-20 spacing).
__global__ __launch_bounds__(256) void select_kernel() {
    int warp = threadIdx.x >> 5, lane = threadIdx.x & 31;
    int b = blockIdx.y;
    int q = blockIdx.x * 8 + warp;
    const __half2* row2 = (const __half2*)(g_dh + ((size_t)b * NN + q) * NN);

    unsigned lkey = 0xFFFFFFFFu;
    unsigned th = 0xFFFFFFFFu;

#pragma unroll 2
    for (int t = 0; t < 32; t++) {
        int j0 = t * 64 + lane * 2;
        __half2 hv = row2[t * 32 + lane];
        unsigned u0 = (unsigned)__half_as_ushort(__low2half(hv));
        unsigned u1 = (unsigned)__half_as_ushort(__high2half(hv));
        unsigned k0 = (u0 << 11) | (unsigned)j0;
        unsigned k1 = (u1 << 11) | (unsigned)(j0 + 1);
#pragma unroll
        for (int h = 0; h < 2; h++) {
            unsigned ck = h ? k1 : k0;
            int j = j0 + h;
            bool pass = (j != q) && (ck < th);
            unsigned bal = __ballot_sync(0xffffffffu, pass);
            while (bal) {
                int src = __ffs(bal) - 1;
                bal &= bal - 1;
                unsigned c2 = __shfl_sync(0xffffffffu, ck, src);
                if (c2 < th) {
                    unsigned up = __shfl_up_sync(0xffffffffu, lkey, 1);
                    if (lkey > c2)
                        lkey = (lane == 0 || up <= c2) ? c2 : up;
                    th = __shfl_sync(0xffffffffu, lkey, 31);
                }
            }
        }
    }
    g_cand[((size_t)b * NN + q) * 32 + lane] = (int)(lkey & 0x7FFu);
}

// ---------------- rescue: exact top-20 among 32 candidates ----------------
// Block per query. Stage 32 candidate rows in SMEM (stride 65 -> conflict-
// free), warp 0 recomputes EXACT distances (verified sequential fmaf chain +
// fma(-2,dot,fadd(sq,sq))), bitonic-sorts 32 monotonic u64 (dist,idx) keys,
// writes ascending top-20 == exact jax top_k order.
__global__ __launch_bounds__(128) void rescue_kernel() {
    __shared__ float rows[32][65];
    __shared__ float qrow[64];
    __shared__ float sqc[32];
    __shared__ int cidx[32];
    __shared__ float sqq_s;

    int tid = threadIdx.x;
    int b = blockIdx.y, q = blockIdx.x;
    const float* xb = g_xt + (size_t)b * NN * 64;

    if (tid < 32) {
        int c = g_cand[((size_t)b * NN + q) * 32 + tid];
        cidx[tid] = c;
        sqc[tid] = g_sq[b * NN + c];
    }
    if (tid < 64) qrow[tid] = xb[(size_t)q * 64 + tid];
    if (tid == 64) sqq_s = g_sq[b * NN + q];
    __syncthreads();
    {
        int r = tid >> 2, ch = tid & 3;
        int src = cidx[r];
        const float4* s4 = (const float4*)(xb + (size_t)src * 64);
#pragma unroll
        for (int u = 0; u < 4; u++) {
            float4 v = s4[ch * 4 + u];
            rows[r][ch * 16 + u * 4 + 0] = v.x;
            rows[r][ch * 16 + u * 4 + 1] = v.y;
            rows[r][ch * 16 + u * 4 + 2] = v.z;
            rows[r][ch * 16 + u * 4 + 3] = v.w;
        }
    }
    __syncthreads();

    if (tid < 32) {
        int lane = tid;
        float dot = 0.f;
#pragma unroll
        for (int c = 0; c < 64; c++)
            dot = __fmaf_rn(qrow[c], rows[lane][c], dot);
        float dist = __fmaf_rn(-2.f, dot, __fadd_rn(sqq_s, sqc[lane]));
        unsigned long long key =
            ((unsigned long long)mono_f(dist) << 32) | (unsigned)cidx[lane];
        // bitonic sort ascending across 32 lanes
#pragma unroll
        for (int k = 2; k <= 32; k <<= 1) {
#pragma unroll
            for (int j = k >> 1; j > 0; j >>= 1) {
                unsigned long long o = __shfl_xor_sync(0xffffffffu, key, j);
                bool up = ((lane & k) == 0);
                bool keep_min = (((lane & j) == 0) == up);
                bool omin = o < key;
                key = (keep_min == omin) ? o : key;
            }
        }
        if (lane < 20)
            g_idx[((size_t)b * NN + q) * 20 + lane] = (int)(key & 0xFFFFFFFFull);
    }
}

// ---------------- edgeconv: mma.sync split-bf16 slotted GEMM ----------------
__global__ __launch_bounds__(256) void edgeconv_mma_kernel(const float* __restrict__ bias,
                                                           float* __restrict__ out) {
    __shared__ __align__(16) __nv_bfloat16 at[128][72];
    __shared__ __align__(16) __nv_bfloat16 wh[64][72];
    __shared__ __align__(16) __nv_bfloat16 wl[64][72];
    __shared__ int idxs[128 * 20];

    int tid = threadIdx.x, wid = tid >> 5, lane = tid & 31;
    int gid = lane >> 2, tig = lane & 3;
    int b = blockIdx.y, n0 = blockIdx.x * 128;
    const char* xhib = (const char*)g_xhi + (size_t)b * NN * 128;
    const char* xlob = (const char*)g_xlo + (size_t)b * NN * 128;

    for (int i = tid; i < 128 * 20; i += 256)
        idxs[i] = g_idx[((size_t)b * NN + n0 + i / 20) * 20 + (i % 20)];

    float acc[8][4];
#pragma unroll
    for (int j = 0; j < 8; j++)
#pragma unroll
        for (int k = 0; k < 4; k++) acc[j][k] = 0.f;

    int arow = wid * 16 + gid;

    for (int slot = 0; slot < 21; slot++) {
        __syncthreads();
#pragma unroll
        for (int i = 0; i < 2; i++) {
            int e = tid + 256 * i;
            int row = e >> 3, ch = e & 7;
            *(uint4*)&wh[row][ch * 8] =
                *(const uint4*)(g_wbh + slot * 4096 + row * 64 + ch * 8);
            *(uint4*)&wl[row][ch * 8] =
                *(const uint4*)(g_wbl + slot * 4096 + row * 64 + ch * 8);
        }
#pragma unroll
        for (int u = 0; u < 4; u++) {
            int i = tid + 256 * u;
            int row = i >> 3, k = i & 7;
            int src = slot ? idxs[row * 20 + slot - 1] : n0 + row;
            *(uint4*)&at[row][k * 8] = *(const uint4*)(xhib + (size_t)src * 128 + k * 16);
        }
        __syncthreads();
#pragma unroll
        for (int kk = 0; kk < 4; kk++) {
            uint32_t a0 = *(const uint32_t*)&at[arow][kk * 16 + tig * 2];
            uint32_t a1 = *(const uint32_t*)&at[arow + 8][kk * 16 + tig * 2];
            uint32_t a2 = *(const uint32_t*)&at[arow][kk * 16 + tig * 2 + 8];
            uint32_t a3 = *(const uint32_t*)&at[arow + 8][kk * 16 + tig * 2 + 8];
#pragma unroll
            for (int j = 0; j < 8; j++) {
                uint32_t b0 = *(const uint32_t*)&wh[j * 8 + gid][kk * 16 + tig * 2];
                uint32_t b1 = *(const uint32_t*)&wh[j * 8 + gid][kk * 16 + tig * 2 + 8];
                mma16816(acc[j], a0, a1, a2, a3, b0, b1);
            }
#pragma unroll
            for (int j = 0; j < 8; j++) {
                uint32_t b0 = *(const uint32_t*)&wl[j * 8 + gid][kk * 16 + tig * 2];
                uint32_t b1 = *(const uint32_t*)&wl[j * 8 + gid][kk * 16 + tig * 2 + 8];
                mma16816(acc[j], a0, a1, a2, a3, b0, b1);
            }
        }
        __syncthreads();
#pragma unroll
        for (int u = 0; u < 4; u++) {
            int i = tid + 256 * u;
            int row = i >> 3, k = i & 7;
            int src = slot ? idxs[row * 20 + slot - 1] : n0 + row;
            *(uint4*)&at[row][k * 8] = *(const uint4*)(xlob + (size_t)src * 128 + k * 16);
        }
        __syncthreads();
#pragma unroll
        for (int kk = 0; kk < 4; kk++) {
            uint32_t a0 = *(const uint32_t*)&at[arow][kk * 16 + tig * 2];
            uint32_t a1 = *(const uint32_t*)&at[arow + 8][kk * 16 + tig * 2];
            uint32_t a2 = *(const uint32_t*)&at[arow][kk * 16 + tig * 2 + 8];
            uint32_t a3 = *(const uint32_t*)&at[arow + 8][kk * 16 + tig * 2 + 8];
#pragma unroll
            for (int j = 0; j < 8; j++) {
                uint32_t b0 = *(const uint32_t*)&wh[j * 8 + gid][kk * 16 + tig * 2];
                uint32_t b1 = *(const uint32_t*)&wh[j * 8 + gid][kk * 16 + tig * 2 + 8];
                mma16816(acc[j], a0, a1, a2, a3, b0, b1);
            }
        }
    }

    float* ob = out + (size_t)b * OUTC * NN;
#pragma unroll
    for (int j = 0; j < 8; j++) {
        int o0 = j * 8 + tig * 2;
        float bv0 = __ldg(bias + o0);
        float bv1 = __ldg(bias + o0 + 1);
        ob[(size_t)o0 * NN + n0 + arow]           = acc[j][0] + bv0;
        ob[(size_t)(o0 + 1) * NN + n0 + arow]     = acc[j][1] + bv1;
        ob[(size_t)o0 * NN + n0 + arow + 8]       = acc[j][2] + bv0;
        ob[(size_t)(o0 + 1) * NN + n0 + arow + 8] = acc[j][3] + bv1;
    }
}

// ---------------- batchnorm stats (one block per channel) ----------------
__global__ void bn_stats_kernel(const float* __restrict__ y,
                                const float* __restrict__ gamma,
                                const float* __restrict__ beta) {
    int o = blockIdx.x, tid = threadIdx.x;
    float s = 0.f, ss = 0.f;
    for (int b = 0; b < BB; b++) {
        const float* p = y + ((size_t)b * OUTC + o) * NN;
        for (int i = tid; i < NN; i += 256) {
            float v = p[i];
            s += v;
            ss = fmaf(v, v, ss);
        }
    }
#pragma unroll
    for (int off = 16; off; off >>= 1) {
        s  += __shfl_down_sync(0xffffffffu, s, off);
        ss += __shfl_down_sync(0xffffffffu, ss, off);
    }
    __shared__ float shs[8], shss[8];
    int w = tid >> 5;
    if ((tid & 31) == 0) { shs[w] = s; shss[w] = ss; }
    __syncthreads();
    if (tid == 0) {
        s = 0.f; ss = 0.f;
#pragma unroll
        for (int k = 0; k < 8; k++) { s += shs[k]; ss += shss[k]; }
        float inv = 1.f / 32768.f;
        float mean = s * inv;
        float var = fmaf(ss, inv, -mean * mean);
        float r = rsqrtf(var + 1e-5f);
        float sc = gamma[o] * r;
        g_scale[o] = sc;
        g_shift[o] = beta[o] - mean * sc;
    }
}

// ---------------- normalize + leaky relu ----------------
__global__ void bn_apply_kernel(float* __restrict__ y) {
    int i = blockIdx.x * 256 + threadIdx.x;
    int o = (i >> 11) & 63;
    float v = fmaf(y[i], g_scale[o], g_shift[o]);
    y[i] = v >= 0.f ? v : 0.2f * v;
}

// ---------------- launch ----------------
extern "C" void kernel_launch(void* const* d_in, const int* in_sizes, int n_in,
                              void* d_out, int out_size) {
    const float* x     = (const float*)d_in[0];  // (16, 64, 2048)
    const float* w     = (const float*)d_in[1];  // (64, 128, 20)
    const float* bias  = (const float*)d_in[2];  // (64,)
    const float* gamma = (const float*)d_in[3];  // (64,)
    const float* beta  = (const float*)d_in[4];  // (64,)
    float* out = (float*)d_out;                  // (16, 64, 2048)

    const int GRAM_SMEM = 4 * 128 * 72 * 2;      // 73728 bytes
    cudaFuncSetAttribute(gram_kernel,
                         cudaFuncAttributeMaxDynamicSharedMemorySize, GRAM_SMEM);

    prep_xt_kernel<<<dim3(NN / 128, BB), 128>>>(x);
    sq_kernel<<<(BB * NN) / 256, 256>>>();
    prep_wb_kernel<<<dim3(21, 16), 256>>>(w);
    gram_kernel<<<dim3(NN / 128, NN / 128, BB), 256, GRAM_SMEM>>>();
    select_kernel<<<dim3(NN / 8, BB), 256>>>();
    rescue_kernel<<<dim3(NN, BB), 128>>>();
    edgeconv_mma_kernel<<<dim3(NN / 128, BB), 256>>>(bias, out);
    bn_stats_kernel<<<OUTC, 256>>>(out, gamma, beta);
    bn_apply_kernel<<<(BB * OUTC * NN) / 256, 256>>>(out);
}

// round 16
// speedup vs baseline: 3.8271x; 1.1055x over previous
#include <cuda_runtime.h>
#include <cuda_bf16.h>
#include <cuda_fp16.h>
#include <cstdint>
#include <cstddef>

// Problem constants
#define BB   16
#define CC   64
#define NN   2048
#define KK   20
#define OUTC 64

// ---------------- scratch (no allocations allowed) ----------------
__device__ __align__(16) float g_xt[BB * NN * CC];     // x transposed: [b][n][c]
__device__ float g_sq[BB * NN];                        // squared norms (bit-exact vs ref)
__device__ int   g_idx[BB * NN * KK];                  // knn indices, ascending dist
__device__ int   g_cand[BB * NN * 32];                 // approx top-32 candidates
__device__ float g_scale[OUTC];
__device__ float g_shift[OUTC];
__device__ float g_bps[OUTC * 32];                     // bn partial sums
__device__ float g_bpss[OUTC * 32];                    // bn partial sumsq
__device__ __align__(16) __half g_dh[(size_t)BB * NN * NN];   // approx distance (fp16, 128MB)
// split-bf16 operands for tensor-core kernels
__device__ __align__(16) __nv_bfloat16 g_xhi[BB * NN * CC];   // [b][n][c]
__device__ __align__(16) __nv_bfloat16 g_xlo[BB * NN * CC];
__device__ __align__(16) __nv_bfloat16 g_wbh[21 * OUTC * CC]; // [slot][o][c]
__device__ __align__(16) __nv_bfloat16 g_wbl[21 * OUTC * CC];

__device__ __forceinline__ void mma16816(float* c, uint32_t a0, uint32_t a1,
                                         uint32_t a2, uint32_t a3,
                                         uint32_t b0, uint32_t b1) {
    asm volatile(
        "mma.sync.aligned.m16n8k16.row.col.f32.bf16.bf16.f32 "
        "{%0,%1,%2,%3}, {%4,%5,%6,%7}, {%8,%9}, {%0,%1,%2,%3};"
        : "+f"(c[0]), "+f"(c[1]), "+f"(c[2]), "+f"(c[3])
        : "r"(a0), "r"(a1), "r"(a2), "r"(a3), "r"(b0), "r"(b1));
}

// monotonic float->uint map (strictly order-preserving incl. negatives)
__device__ __forceinline__ unsigned mono_f(float f) {
    unsigned u = __float_as_uint(f);
    return u ^ (((unsigned)((int)u >> 31)) | 0x80000000u);
}

// ---------------- prep: transpose x -> xt (+ bf16 hi/lo split) ----------------
__global__ void prep_xt_kernel(const float* __restrict__ x) {
    __shared__ float sm[64][129];
    int b = blockIdx.y, n0 = blockIdx.x * 128, t = threadIdx.x;
    const float* xb = x + (size_t)b * CC * NN;
#pragma unroll
    for (int c = 0; c < 64; c++)
        sm[c][t] = xb[(size_t)c * NN + n0 + t];
    __syncthreads();
    float* xtb = g_xt + ((size_t)b * NN + n0) * 64;
    __nv_bfloat16* xh = g_xhi + ((size_t)b * NN + n0) * 64;
    __nv_bfloat16* xl = g_xlo + ((size_t)b * NN + n0) * 64;
#pragma unroll 4
    for (int i = 0; i < 64; i++) {
        int flat = i * 128 + t;
        int c = flat & 63, p = flat >> 6;
        float v = sm[c][p];
        xtb[(size_t)p * 64 + c] = v;
        __nv_bfloat16 h = __float2bfloat16(v);
        xh[(size_t)p * 64 + c] = h;
        xl[(size_t)p * 64 + c] = __float2bfloat16(v - __bfloat162float(h));
    }
}

// ---------------- sq: XLA:CPU + LLVM LoopVectorizer replica ----------------
// VF=4 (NEON), IC=2 -> 8 mod-8 lanes; verified bit-exact in round 7.
__global__ __launch_bounds__(256) void sq_kernel() {
    int p = blockIdx.x * 256 + threadIdx.x;
    const float4* z = (const float4*)(g_xt + (size_t)p * 64);
    float a[8];
#pragma unroll
    for (int l = 0; l < 8; l++) a[l] = 0.f;
#pragma unroll
    for (int i = 0; i < 8; i++) {
        float4 v0 = z[2 * i];
        float4 v1 = z[2 * i + 1];
        a[0] = __fadd_rn(a[0], __fmul_rn(v0.x, v0.x));
        a[1] = __fadd_rn(a[1], __fmul_rn(v0.y, v0.y));
        a[2] = __fadd_rn(a[2], __fmul_rn(v0.z, v0.z));
        a[3] = __fadd_rn(a[3], __fmul_rn(v0.w, v0.w));
        a[4] = __fadd_rn(a[4], __fmul_rn(v1.x, v1.x));
        a[5] = __fadd_rn(a[5], __fmul_rn(v1.y, v1.y));
        a[6] = __fadd_rn(a[6], __fmul_rn(v1.z, v1.z));
        a[7] = __fadd_rn(a[7], __fmul_rn(v1.w, v1.w));
    }
    float t0 = __fadd_rn(a[0], a[4]);
    float t1 = __fadd_rn(a[1], a[5]);
    float t2 = __fadd_rn(a[2], a[6]);
    float t3 = __fadd_rn(a[3], a[7]);
    g_sq[p] = __fadd_rn(__fadd_rn(t0, t1), __fadd_rn(t2, t3));
}

// ---------------- prep: split weights -> bf16 hi/lo, [slot][o][c] ----------
__global__ void prep_wb_kernel(const float* __restrict__ w) {
    int slot = blockIdx.x;
    int e = blockIdx.y * 256 + threadIdx.x;   // 0..4095
    int o = e >> 6, c = e & 63;
    float val;
    if (slot == 0) {
        float s = 0.f;
        const float* w1 = w + ((size_t)o * 128 + c) * 20;
        const float* w2 = w + ((size_t)o * 128 + 64 + c) * 20;
#pragma unroll
        for (int j = 0; j < 20; j++) s += w1[j] - w2[j];
        val = s;
    } else {
        val = w[((size_t)o * 128 + 64 + c) * 20 + slot - 1];
    }
    __nv_bfloat16 h = __float2bfloat16(val);
    __nv_bfloat16 l = __float2bfloat16(val - __bfloat162float(h));
    g_wbh[slot * 4096 + o * 64 + c] = h;
    g_wbl[slot * 4096 + o * 64 + c] = l;
}

// ---------------- gram: approx distance matrix (plain bf16, single pass) ----
// Candidate stage only: hh-pass error (~0.06 abs) + fp16 store (~0.06) is
// >10 sigma below the rank-20..32 margin, so approx top-32 remains a superset
// of the exact top-20 (rescue recomputes exactly).
// CTA tile 128(i) x 128(j), 8 warps; warp = 16 i-rows x 128 j-cols.
__global__ __launch_bounds__(256) void gram_kernel() {
    __shared__ __align__(16) __nv_bfloat16 ah[128 * 72];
    __shared__ __align__(16) __nv_bfloat16 bh[128 * 72];

    int tid = threadIdx.x, wid = tid >> 5, lane = tid & 31;
    int gid = lane >> 2, tig = lane & 3;
    int b = blockIdx.z;
    int i0 = blockIdx.y * 128, j0 = blockIdx.x * 128;
    const uint4* xh = (const uint4*)(g_xhi + (size_t)b * NN * 64);  // 8 uint4 per row

#pragma unroll
    for (int u = 0; u < 4; u++) {
        int e = tid + 256 * u;
        int r = e >> 3, ch = e & 7;
        *(uint4*)&ah[r * 72 + ch * 8] = xh[(size_t)(i0 + r) * 8 + ch];
        *(uint4*)&bh[r * 72 + ch * 8] = xh[(size_t)(j0 + r) * 8 + ch];
    }
    __syncthreads();

    int arow = wid * 16 + gid;
    float acc[16][4];
#pragma unroll
    for (int nb = 0; nb < 16; nb++)
#pragma unroll
        for (int k = 0; k < 4; k++) acc[nb][k] = 0.f;

#pragma unroll
    for (int kk = 0; kk < 4; kk++) {
        int co = kk * 16 + tig * 2;
        uint32_t a0 = *(const uint32_t*)&ah[arow * 72 + co];
        uint32_t a1 = *(const uint32_t*)&ah[(arow + 8) * 72 + co];
        uint32_t a2 = *(const uint32_t*)&ah[arow * 72 + co + 8];
        uint32_t a3 = *(const uint32_t*)&ah[(arow + 8) * 72 + co + 8];
#pragma unroll
        for (int nb = 0; nb < 16; nb++) {
            uint32_t b0 = *(const uint32_t*)&bh[(nb * 8 + gid) * 72 + co];
            uint32_t b1 = *(const uint32_t*)&bh[(nb * 8 + gid) * 72 + co + 8];
            mma16816(acc[nb], a0, a1, a2, a3, b0, b1);
        }
    }

    float si0 = g_sq[b * NN + i0 + arow];
    float si8 = g_sq[b * NN + i0 + arow + 8];
    __half* db = g_dh + (size_t)b * NN * NN;
#pragma unroll
    for (int nb = 0; nb < 16; nb++) {
        int jj = j0 + nb * 8 + tig * 2;
        float sj0 = g_sq[b * NN + jj];
        float sj1 = g_sq[b * NN + jj + 1];
        float d00 = fmaxf(__fmaf_rn(-2.f, acc[nb][0], __fadd_rn(si0, sj0)), 0.f);
        float d01 = fmaxf(__fmaf_rn(-2.f, acc[nb][1], __fadd_rn(si0, sj1)), 0.f);
        float d80 = fmaxf(__fmaf_rn(-2.f, acc[nb][2], __fadd_rn(si8, sj0)), 0.f);
        float d81 = fmaxf(__fmaf_rn(-2.f, acc[nb][3], __fadd_rn(si8, sj1)), 0.f);
        *(__half2*)&db[(size_t)(i0 + arow) * NN + jj]     = __floats2half2_rn(d00, d01);
        *(__half2*)&db[(size_t)(i0 + arow + 8) * NN + jj] = __floats2half2_rn(d80, d81);
    }
}

// ---------------- select: warp-cooperative approx top-32 ----------------
__global__ __launch_bounds__(256) void select_kernel() {
    int warp = threadIdx.x >> 5, lane = threadIdx.x & 31;
    int b = blockIdx.y;
    int q = blockIdx.x * 8 + warp;
    const __half2* row2 = (const __half2*)(g_dh + ((size_t)b * NN + q) * NN);

    unsigned lkey = 0xFFFFFFFFu;
    unsigned th = 0xFFFFFFFFu;

#pragma unroll 2
    for (int t = 0; t < 32; t++) {
        int j0 = t * 64 + lane * 2;
        __half2 hv = row2[t * 32 + lane];
        unsigned u0 = (unsigned)__half_as_ushort(__low2half(hv));
        unsigned u1 = (unsigned)__half_as_ushort(__high2half(hv));
        unsigned k0 = (u0 << 11) | (unsigned)j0;
        unsigned k1 = (u1 << 11) | (unsigned)(j0 + 1);
#pragma unroll
        for (int h = 0; h < 2; h++) {
            unsigned ck = h ? k1 : k0;
            int j = j0 + h;
            bool pass = (j != q) && (ck < th);
            unsigned bal = __ballot_sync(0xffffffffu, pass);
            while (bal) {
                int src = __ffs(bal) - 1;
                bal &= bal - 1;
                unsigned c2 = __shfl_sync(0xffffffffu, ck, src);
                if (c2 < th) {
                    unsigned up = __shfl_up_sync(0xffffffffu, lkey, 1);
                    if (lkey > c2)
                        lkey = (lane == 0 || up <= c2) ? c2 : up;
                    th = __shfl_sync(0xffffffffu, lkey, 31);
                }
            }
        }
    }
    g_cand[((size_t)b * NN + q) * 32 + lane] = (int)(lkey & 0x7FFu);
}

// ---------------- rescue: exact top-20 among 32 candidates ----------------
__global__ __launch_bounds__(128) void rescue_kernel() {
    __shared__ float rows[32][65];
    __shared__ float qrow[64];
    __shared__ float sqc[32];
    __shared__ int cidx[32];
    __shared__ float sqq_s;

    int tid = threadIdx.x;
    int b = blockIdx.y, q = blockIdx.x;
    const float* xb = g_xt + (size_t)b * NN * 64;

    if (tid < 32) {
        int c = g_cand[((size_t)b * NN + q) * 32 + tid];
        cidx[tid] = c;
        sqc[tid] = g_sq[b * NN + c];
    }
    if (tid < 64) qrow[tid] = xb[(size_t)q * 64 + tid];
    if (tid == 64) sqq_s = g_sq[b * NN + q];
    __syncthreads();
    {
        int r = tid >> 2, ch = tid & 3;
        int src = cidx[r];
        const float4* s4 = (const float4*)(xb + (size_t)src * 64);
#pragma unroll
        for (int u = 0; u < 4; u++) {
            float4 v = s4[ch * 4 + u];
            rows[r][ch * 16 + u * 4 + 0] = v.x;
            rows[r][ch * 16 + u * 4 + 1] = v.y;
            rows[r][ch * 16 + u * 4 + 2] = v.z;
            rows[r][ch * 16 + u * 4 + 3] = v.w;
        }
    }
    __syncthreads();

    if (tid < 32) {
        int lane = tid;
        float dot = 0.f;
#pragma unroll
        for (int c = 0; c < 64; c++)
            dot = __fmaf_rn(qrow[c], rows[lane][c], dot);
        float dist = __fmaf_rn(-2.f, dot, __fadd_rn(sqq_s, sqc[lane]));
        unsigned long long key =
            ((unsigned long long)mono_f(dist) << 32) | (unsigned)cidx[lane];
#pragma unroll
        for (int k = 2; k <= 32; k <<= 1) {
#pragma unroll
            for (int j = k >> 1; j > 0; j >>= 1) {
                unsigned long long o = __shfl_xor_sync(0xffffffffu, key, j);
                bool up = ((lane & k) == 0);
                bool keep_min = (((lane & j) == 0) == up);
                bool omin = o < key;
                key = (keep_min == omin) ? o : key;
            }
        }
        if (lane < 20)
            g_idx[((size_t)b * NN + q) * 20 + lane] = (int)(key & 0xFFFFFFFFull);
    }
}

// ---------------- edgeconv: mma.sync split-bf16 slotted GEMM ----------------
__global__ __launch_bounds__(256) void edgeconv_mma_kernel(const float* __restrict__ bias,
                                                           float* __restrict__ out) {
    __shared__ __align__(16) __nv_bfloat16 at[128][72];
    __shared__ __align__(16) __nv_bfloat16 wh[64][72];
    __shared__ __align__(16) __nv_bfloat16 wl[64][72];
    __shared__ int idxs[128 * 20];

    int tid = threadIdx.x, wid = tid >> 5, lane = tid & 31;
    int gid = lane >> 2, tig = lane & 3;
    int b = blockIdx.y, n0 = blockIdx.x * 128;
    const char* xhib = (const char*)g_xhi + (size_t)b * NN * 128;
    const char* xlob = (const char*)g_xlo + (size_t)b * NN * 128;

    for (int i = tid; i < 128 * 20; i += 256)
        idxs[i] = g_idx[((size_t)b * NN + n0 + i / 20) * 20 + (i % 20)];

    float acc[8][4];
#pragma unroll
    for (int j = 0; j < 8; j++)
#pragma unroll
        for (int k = 0; k < 4; k++) acc[j][k] = 0.f;

    int arow = wid * 16 + gid;

    for (int slot = 0; slot < 21; slot++) {
        __syncthreads();
#pragma unroll
        for (int i = 0; i < 2; i++) {
            int e = tid + 256 * i;
            int row = e >> 3, ch = e & 7;
            *(uint4*)&wh[row][ch * 8] =
                *(const uint4*)(g_wbh + slot * 4096 + row * 64 + ch * 8);
            *(uint4*)&wl[row][ch * 8] =
                *(const uint4*)(g_wbl + slot * 4096 + row * 64 + ch * 8);
        }
#pragma unroll
        for (int u = 0; u < 4; u++) {
            int i = tid + 256 * u;
            int row = i >> 3, k = i & 7;
            int src = slot ? idxs[row * 20 + slot - 1] : n0 + row;
            *(uint4*)&at[row][k * 8] = *(const uint4*)(xhib + (size_t)src * 128 + k * 16);
        }
        __syncthreads();
#pragma unroll
        for (int kk = 0; kk < 4; kk++) {
            uint32_t a0 = *(const uint32_t*)&at[arow][kk * 16 + tig * 2];
            uint32_t a1 = *(const uint32_t*)&at[arow + 8][kk * 16 + tig * 2];
            uint32_t a2 = *(const uint32_t*)&at[arow][kk * 16 + tig * 2 + 8];
            uint32_t a3 = *(const uint32_t*)&at[arow + 8][kk * 16 + tig * 2 + 8];
#pragma unroll
            for (int j = 0; j < 8; j++) {
                uint32_t b0 = *(const uint32_t*)&wh[j * 8 + gid][kk * 16 + tig * 2];
                uint32_t b1 = *(const uint32_t*)&wh[j * 8 + gid][kk * 16 + tig * 2 + 8];
                mma16816(acc[j], a0, a1, a2, a3, b0, b1);
            }
#pragma unroll
            for (int j = 0; j < 8; j++) {
                uint32_t b0 = *(const uint32_t*)&wl[j * 8 + gid][kk * 16 + tig * 2];
                uint32_t b1 = *(const uint32_t*)&wl[j * 8 + gid][kk * 16 + tig * 2 + 8];
                mma16816(acc[j], a0, a1, a2, a3, b0, b1);
            }
        }
        __syncthreads();
#pragma unroll
        for (int u = 0; u < 4; u++) {
            int i = tid + 256 * u;
            int row = i >> 3, k = i & 7;
            int src = slot ? idxs[row * 20 + slot - 1] : n0 + row;
            *(uint4*)&at[row][k * 8] = *(const uint4*)(xlob + (size_t)src * 128 + k * 16);
        }
        __syncthreads();
#pragma unroll
        for (int kk = 0; kk < 4; kk++) {
            uint32_t a0 = *(const uint32_t*)&at[arow][kk * 16 + tig * 2];
            uint32_t a1 = *(const uint32_t*)&at[arow + 8][kk * 16 + tig * 2];
            uint32_t a2 = *(const uint32_t*)&at[arow][kk * 16 + tig * 2 + 8];
            uint32_t a3 = *(const uint32_t*)&at[arow + 8][kk * 16 + tig * 2 + 8];
#pragma unroll
            for (int j = 0; j < 8; j++) {
                uint32_t b0 = *(const uint32_t*)&wh[j * 8 + gid][kk * 16 + tig * 2];
                uint32_t b1 = *(const uint32_t*)&wh[j * 8 + gid][kk * 16 + tig * 2 + 8];
                mma16816(acc[j], a0, a1, a2, a3, b0, b1);
            }
        }
    }

    float* ob = out + (size_t)b * OUTC * NN;
#pragma unroll
    for (int j = 0; j < 8; j++) {
        int o0 = j * 8 + tig * 2;
        float bv0 = __ldg(bias + o0);
        float bv1 = __ldg(bias + o0 + 1);
        ob[(size_t)o0 * NN + n0 + arow]           = acc[j][0] + bv0;
        ob[(size_t)(o0 + 1) * NN + n0 + arow]     = acc[j][1] + bv1;
        ob[(size_t)o0 * NN + n0 + arow + 8]       = acc[j][2] + bv0;
        ob[(size_t)(o0 + 1) * NN + n0 + arow + 8] = acc[j][3] + bv1;
    }
}

// ---------------- batchnorm: two-stage deterministic reduction ----------------
__global__ __launch_bounds__(256) void bn_part_kernel(const float* __restrict__ y) {
    int o = blockIdx.y, chunk = blockIdx.x;          // 32 chunks of 1024
    int tid = threadIdx.x;
    const float* p = y + ((size_t)(chunk >> 1) * OUTC + o) * NN + (chunk & 1) * 1024;
    float s = 0.f, ss = 0.f;
#pragma unroll
    for (int u = 0; u < 4; u++) {
        float v = p[tid + 256 * u];
        s += v;
        ss = fmaf(v, v, ss);
    }
#pragma unroll
    for (int off = 16; off; off >>= 1) {
        s  += __shfl_down_sync(0xffffffffu, s, off);
        ss += __shfl_down_sync(0xffffffffu, ss, off);
    }
    __shared__ float shs[8], shss[8];
    int w = tid >> 5;
    if ((tid & 31) == 0) { shs[w] = s; shss[w] = ss; }
    __syncthreads();
    if (tid == 0) {
        s = 0.f; ss = 0.f;
#pragma unroll
        for (int k = 0; k < 8; k++) { s += shs[k]; ss += shss[k]; }
        g_bps[o * 32 + chunk] = s;
        g_bpss[o * 32 + chunk] = ss;
    }
}

__global__ void bn_final_kernel(const float* __restrict__ gamma,
                                const float* __restrict__ beta) {
    int o = threadIdx.x;    // 64 threads
    float s = 0.f, ss = 0.f;
#pragma unroll
    for (int k = 0; k < 32; k++) {
        s += g_bps[o * 32 + k];
        ss += g_bpss[o * 32 + k];
    }
    float inv = 1.f / 32768.f;
    float mean = s * inv;
    float var = fmaf(ss, inv, -mean * mean);
    float r = rsqrtf(var + 1e-5f);
    float sc = gamma[o] * r;
    g_scale[o] = sc;
    g_shift[o] = beta[o] - mean * sc;
}

// ---------------- normalize + leaky relu ----------------
__global__ void bn_apply_kernel(float* __restrict__ y) {
    int i = blockIdx.x * 256 + threadIdx.x;
    int o = (i >> 11) & 63;
    float v = fmaf(y[i], g_scale[o], g_shift[o]);
    y[i] = v >= 0.f ? v : 0.2f * v;
}

// ---------------- launch ----------------
extern "C" void kernel_launch(void* const* d_in, const int* in_sizes, int n_in,
                              void* d_out, int out_size) {
    const float* x     = (const float*)d_in[0];  // (16, 64, 2048)
    const float* w     = (const float*)d_in[1];  // (64, 128, 20)
    const float* bias  = (const float*)d_in[2];  // (64,)
    const float* gamma = (const float*)d_in[3];  // (64,)
    const float* beta  = (const float*)d_in[4];  // (64,)
    float* out = (float*)d_out;                  // (16, 64, 2048)

    prep_xt_kernel<<<dim3(NN / 128, BB), 128>>>(x);
    sq_kernel<<<(BB * NN) / 256, 256>>>();
    prep_wb_kernel<<<dim3(21, 16), 256>>>(w);
    gram_kernel<<<dim3(NN / 128, NN / 128, BB), 256>>>();
    select_kernel<<<dim3(NN / 8, BB), 256>>>();
    rescue_kernel<<<dim3(NN, BB), 128>>>();
    edgeconv_mma_kernel<<<dim3(NN / 128, BB), 256>>>(bias, out);
    bn_part_kernel<<<dim3(32, OUTC), 256>>>(out);
    bn_final_kernel<<<1, OUTC>>>(gamma, beta);
    bn_apply_kernel<<<(BB * OUTC * NN) / 256, 256>>>(out);
}